// round 2
// baseline (speedup 1.0000x reference)
#include <cuda_runtime.h>
#include <cuda_bf16.h>

// ---------------- problem constants ----------------
#define Bb 4
#define Tt 2048
#define Ee 512
#define Hh 8
#define Ll 5
#define Vv 130
#define Dd 512
#define TD (Tt * Dd)
#define TT (Tt * Tt)

// ---------------- device scratch (allocation-free rule: __device__ globals) ----------------
__device__ float g_y[Bb * Tt * Ee];                  // residual stream
__device__ float g_h[Bb * Tt * Ee];                  // LN output / h2
__device__ float g_q[Bb * Hh * Tt * Dd];             // Q [B,H,T,D]
__device__ float g_k[Bb * Hh * Tt * Dd];             // K
__device__ float g_v[Bb * Hh * Tt * Dd];             // V
__device__ float g_s[(long long)Bb * Hh * Tt * Tt];  // scores [B*H,T,T]
__device__ float g_ao[Bb * Hh * Tt * Dd];            // per-head attn out
__device__ float g_u[Bb * Tt * 4 * Ee];              // MLP hidden

// ---------------- GEMM ----------------
// C = A * op(B), A row-major [M,K]; BNT=true: B row-major [N,K] (NT); false: [K,N] (NN)
constexpr int BM = 128, BN = 128, BK = 16, TM = 8, TN = 8;

enum { EPI_PLAIN = 0, EPI_QKV = 1, EPI_CAUSAL = 2, EPI_BIASRELU = 3, EPI_BIASRES = 4 };

template <bool BNT, int EPI, bool CK>
__global__ __launch_bounds__(256, 2) void gemm_kernel(
    const float* __restrict__ A, const float* __restrict__ B, float* __restrict__ C,
    int M, int N, int K,
    long long sA, long long sB, long long sC,
    const float* __restrict__ bias, const float* __restrict__ Res)
{
    const int bx = blockIdx.x, by = blockIdx.y, bz = blockIdx.z;
    if (EPI == EPI_CAUSAL && bx > by) return;   // skip strictly-upper tiles

    A += (long long)bz * sA;
    B += (long long)bz * sB;
    C += (long long)bz * sC;

    int Keff = K;
    if (CK) { int ke = (by + 1) * BM; Keff = ke < K ? ke : K; }  // causal K-bound for AV

    __shared__ float As[BK][BM];
    __shared__ float Bs[BK][BN];

    const int tid = threadIdx.x;
    const int tx = tid & 15, ty = tid >> 4;
    const int m0 = by * BM, n0 = bx * BN;

    float acc[TM][TN];
#pragma unroll
    for (int i = 0; i < TM; i++)
#pragma unroll
        for (int j = 0; j < TN; j++) acc[i][j] = 0.f;

    const int aRow = tid >> 2;            // 0..63
    const int aCol = (tid & 3) << 2;      // 0,4,8,12
    const int bRowN = tid >> 5;           // 0..7
    const int bColN = (tid & 31) << 2;    // 0..124

    for (int kt = 0; kt < Keff; kt += BK) {
#pragma unroll
        for (int r = 0; r < BM; r += 64) {
            float4 v = *reinterpret_cast<const float4*>(&A[(long long)(m0 + aRow + r) * K + kt + aCol]);
            As[aCol + 0][aRow + r] = v.x;
            As[aCol + 1][aRow + r] = v.y;
            As[aCol + 2][aRow + r] = v.z;
            As[aCol + 3][aRow + r] = v.w;
        }
        if (BNT) {
#pragma unroll
            for (int r = 0; r < BN; r += 64) {
                float4 v = *reinterpret_cast<const float4*>(&B[(long long)(n0 + aRow + r) * K + kt + aCol]);
                Bs[aCol + 0][aRow + r] = v.x;
                Bs[aCol + 1][aRow + r] = v.y;
                Bs[aCol + 2][aRow + r] = v.z;
                Bs[aCol + 3][aRow + r] = v.w;
            }
        } else {
#pragma unroll
            for (int r = 0; r < BK; r += 8) {
                float4 v = *reinterpret_cast<const float4*>(&B[(long long)(kt + bRowN + r) * N + n0 + bColN]);
                *reinterpret_cast<float4*>(&Bs[bRowN + r][bColN]) = v;
            }
        }
        __syncthreads();

#pragma unroll
        for (int kk = 0; kk < BK; kk++) {
            float a[TM], b[TN];
#pragma unroll
            for (int i = 0; i < TM; i += 4)
                *reinterpret_cast<float4*>(&a[i]) = *reinterpret_cast<const float4*>(&As[kk][ty * TM + i]);
#pragma unroll
            for (int j = 0; j < TN; j += 4)
                *reinterpret_cast<float4*>(&b[j]) = *reinterpret_cast<const float4*>(&Bs[kk][tx * TN + j]);
#pragma unroll
            for (int i = 0; i < TM; i++)
#pragma unroll
                for (int j = 0; j < TN; j++) acc[i][j] = fmaf(a[i], b[j], acc[i][j]);
        }
        __syncthreads();
    }

#pragma unroll
    for (int i = 0; i < TM; i++) {
        const int m = m0 + ty * TM + i;
#pragma unroll
        for (int j = 0; j < TN; j++) {
            const int n = n0 + tx * TN + j;
            float v = acc[i][j];
            if (EPI == EPI_PLAIN) {
                C[(long long)m * N + n] = v;
            } else if (EPI == EPI_QKV) {
                const int b_ = m >> 11, t = m & (Tt - 1);
                const int h = n >> 9, d = n & (Dd - 1);
                C[((long long)(b_ * Hh + h) << 20) + ((long long)t << 9) + d] = v;
            } else if (EPI == EPI_CAUSAL) {
                v *= 0.044194173824159216f;  // 512^-0.5
                if (n > m) v = -1e30f;
                C[(long long)m * N + n] = v;
            } else if (EPI == EPI_BIASRELU) {
                v += bias[n];
                C[(long long)m * N + n] = fmaxf(v, 0.f);
            } else {  // EPI_BIASRES
                v += bias[n] + Res[(long long)m * N + n];
                C[(long long)m * N + n] = v;
            }
        }
    }
}

// ---------------- LayerNorm: one block per row of 512 ----------------
__global__ void ln_kernel(const float* __restrict__ x, const float* __restrict__ g,
                          const float* __restrict__ b, float* __restrict__ out)
{
    const int row = blockIdx.x;
    const float* xr = x + (long long)row * Ee;
    const int tid = threadIdx.x;  // 256
    float v0 = xr[tid], v1 = xr[tid + 256];
    float s = v0 + v1, sq = v0 * v0 + v1 * v1;
#pragma unroll
    for (int o = 16; o; o >>= 1) {
        s  += __shfl_xor_sync(0xffffffffu, s,  o);
        sq += __shfl_xor_sync(0xffffffffu, sq, o);
    }
    __shared__ float ss[8], sqq[8];
    const int warp = tid >> 5, lane = tid & 31;
    if (lane == 0) { ss[warp] = s; sqq[warp] = sq; }
    __syncthreads();
    if (tid == 0) {
        float a = 0.f, c = 0.f;
#pragma unroll
        for (int i = 0; i < 8; i++) { a += ss[i]; c += sqq[i]; }
        ss[0] = a; sqq[0] = c;
    }
    __syncthreads();
    const float mu  = ss[0] * (1.f / 512.f);
    const float var = sqq[0] * (1.f / 512.f) - mu * mu;
    const float r = rsqrtf(var + 1e-5f);
    out[(long long)row * Ee + tid]       = (v0 - mu) * r * g[tid]       + b[tid];
    out[(long long)row * Ee + tid + 256] = (v1 - mu) * r * g[tid + 256] + b[tid + 256];
}

// ---------------- causal softmax: one block (256 thr) per row, float4 ----------------
__global__ void softmax_kernel(float* __restrict__ S)
{
    const long long r = blockIdx.x;        // 0 .. B*H*T-1
    const int t = (int)(r & (Tt - 1));
    float* row = S + (r << 11);
    const int len4 = (((t >> 7) + 1) << 7) >> 2;  // valid float4 count (tile-aligned)
    const int tid = threadIdx.x;           // 256

    float4 e[2];
    float mx = -1e30f;
#pragma unroll
    for (int c = 0; c < 2; c++) {
        const int i = tid + c * 256;       // float4 index, max 512
        if (i < len4) {
            e[c] = *reinterpret_cast<const float4*>(&row[i << 2]);
            mx = fmaxf(fmaxf(fmaxf(e[c].x, e[c].y), fmaxf(e[c].z, e[c].w)), mx);
        }
    }
    __shared__ float redmax[8], redsum[8];
#pragma unroll
    for (int o = 16; o; o >>= 1) mx = fmaxf(mx, __shfl_xor_sync(0xffffffffu, mx, o));
    const int warp = tid >> 5, lane = tid & 31;
    if (lane == 0) redmax[warp] = mx;
    __syncthreads();
    mx = redmax[0];
#pragma unroll
    for (int w = 1; w < 8; w++) mx = fmaxf(mx, redmax[w]);

    float sum = 0.f;
#pragma unroll
    for (int c = 0; c < 2; c++) {
        const int i = tid + c * 256;
        if (i < len4) {
            e[c].x = expf(e[c].x - mx); e[c].y = expf(e[c].y - mx);
            e[c].z = expf(e[c].z - mx); e[c].w = expf(e[c].w - mx);
            sum += (e[c].x + e[c].y) + (e[c].z + e[c].w);
        }
    }
#pragma unroll
    for (int o = 16; o; o >>= 1) sum += __shfl_xor_sync(0xffffffffu, sum, o);
    if (lane == 0) redsum[warp] = sum;
    __syncthreads();
    sum = 0.f;
#pragma unroll
    for (int w = 0; w < 8; w++) sum += redsum[w];
    const float inv = 1.f / sum;
#pragma unroll
    for (int c = 0; c < 2; c++) {
        const int i = tid + c * 256;
        if (i < len4) {
            e[c].x *= inv; e[c].y *= inv; e[c].z *= inv; e[c].w *= inv;
            *reinterpret_cast<float4*>(&row[i << 2]) = e[c];
        }
    }
}

// ---------------- embedding ----------------
__global__ void embed_kernel(const int* __restrict__ tokens, const float* __restrict__ emb,
                             const float* __restrict__ pos, float* __restrict__ y)
{
    const long long idx = (long long)blockIdx.x * 256 + threadIdx.x;  // B*T*E
    const int e = (int)(idx & (Ee - 1));
    const long long m = idx >> 9;            // b*T + t
    const int t = (int)(m & (Tt - 1));
    const int tok = tokens[m];
    y[idx] = emb[(long long)tok * Ee + e] + pos[(long long)t * Ee + e];
}

// ---------------- head sum + residual: y += sum_h ao (float4) ----------------
__global__ void headsum_kernel(const float* __restrict__ ao, float* __restrict__ y)
{
    const long long i4 = (long long)blockIdx.x * 256 + threadIdx.x;  // float4 index, B*T*E/4
    const long long idx = i4 << 2;
    const int e = (int)(idx & (Ee - 1));
    const long long m = idx >> 9;
    const int b_ = (int)(m >> 11);
    const int t = (int)(m & (Tt - 1));
    float4 s = *reinterpret_cast<const float4*>(&y[idx]);
    const long long base = ((long long)(b_ * Hh) << 20) + ((long long)t << 9) + e;
#pragma unroll
    for (int h = 0; h < Hh; h++) {
        float4 a = *reinterpret_cast<const float4*>(&ao[base + ((long long)h << 20)]);
        s.x += a.x; s.y += a.y; s.z += a.z; s.w += a.w;
    }
    *reinterpret_cast<float4*>(&y[idx]) = s;
}

// ---------------- logits: warp per row, N=130 ----------------
__global__ void logits_kernel(const float* __restrict__ y, const float* __restrict__ Wout,
                              const float* __restrict__ bout, float* __restrict__ out)
{
    const int warp = threadIdx.x >> 5, lane = threadIdx.x & 31;
    const int m = blockIdx.x * 8 + warp;
    const float* yr = y + (long long)m * Ee;
    float yreg[16];
#pragma unroll
    for (int i = 0; i < 16; i++) yreg[i] = yr[lane + i * 32];
    for (int n = 0; n < Vv; n++) {
        const float* w = Wout + (long long)n * Ee;
        float s = 0.f;
#pragma unroll
        for (int i = 0; i < 16; i++) s = fmaf(yreg[i], w[lane + i * 32], s);
#pragma unroll
        for (int o = 16; o; o >>= 1) s += __shfl_xor_sync(0xffffffffu, s, o);
        if (lane == 0) out[(long long)m * Vv + n] = s + bout[n];
    }
}

// ---------------- driver ----------------
extern "C" void kernel_launch(void* const* d_in, const int* in_sizes, int n_in,
                              void* d_out, int out_size)
{
    const int*   tokens = (const int*)  d_in[0];
    const float* emb    = (const float*)d_in[1];
    const float* pos    = (const float*)d_in[2];
    const float* ln1_g  = (const float*)d_in[3];
    const float* ln1_b  = (const float*)d_in[4];
    const float* Wq     = (const float*)d_in[5];
    const float* Wk     = (const float*)d_in[6];
    const float* Wv     = (const float*)d_in[7];
    const float* ln2_g  = (const float*)d_in[8];
    const float* ln2_b  = (const float*)d_in[9];
    const float* W1     = (const float*)d_in[10];
    const float* b1     = (const float*)d_in[11];
    const float* W2     = (const float*)d_in[12];
    const float* b2     = (const float*)d_in[13];
    const float* Wout   = (const float*)d_in[14];
    const float* bout   = (const float*)d_in[15];
    float* out = (float*)d_out;

    float *y, *h, *q, *k, *v, *s, *ao, *u;
    cudaGetSymbolAddress((void**)&y,  g_y);
    cudaGetSymbolAddress((void**)&h,  g_h);
    cudaGetSymbolAddress((void**)&q,  g_q);
    cudaGetSymbolAddress((void**)&k,  g_k);
    cudaGetSymbolAddress((void**)&v,  g_v);
    cudaGetSymbolAddress((void**)&s,  g_s);
    cudaGetSymbolAddress((void**)&ao, g_ao);
    cudaGetSymbolAddress((void**)&u,  g_u);

    const int MBT = Bb * Tt;                 // 8192
    const long long WqkvStride = (long long)Hh * Dd * Ee;

    embed_kernel<<<(MBT * Ee) / 256, 256>>>(tokens, emb, pos, y);

    for (int l = 0; l < Ll; l++) {
        ln_kernel<<<MBT, 256>>>(y, ln1_g + l * Ee, ln1_b + l * Ee, h);

        dim3 gqkv(4096 / BN, MBT / BM);
        gemm_kernel<true, EPI_QKV, false><<<gqkv, 256>>>(h, Wq + l * WqkvStride, q,
            MBT, Hh * Dd, Ee, 0, 0, 0, nullptr, nullptr);
        gemm_kernel<true, EPI_QKV, false><<<gqkv, 256>>>(h, Wk + l * WqkvStride, k,
            MBT, Hh * Dd, Ee, 0, 0, 0, nullptr, nullptr);
        gemm_kernel<true, EPI_QKV, false><<<gqkv, 256>>>(h, Wv + l * WqkvStride, v,
            MBT, Hh * Dd, Ee, 0, 0, 0, nullptr, nullptr);

        dim3 gqk(Tt / BN, Tt / BM, Bb * Hh);
        gemm_kernel<true, EPI_CAUSAL, false><<<gqk, 256>>>(q, k, s,
            Tt, Tt, Dd, (long long)TD, (long long)TD, (long long)TT, nullptr, nullptr);

        softmax_kernel<<<Bb * Hh * Tt, 256>>>(s);

        dim3 gav(Dd / BN, Tt / BM, Bb * Hh);
        gemm_kernel<false, EPI_PLAIN, true><<<gav, 256>>>(s, v, ao,
            Tt, Dd, Tt, (long long)TT, (long long)TD, (long long)TD, nullptr, nullptr);

        headsum_kernel<<<(MBT * Ee) / 1024, 256>>>(ao, y);

        ln_kernel<<<MBT, 256>>>(y, ln2_g + l * Ee, ln2_b + l * Ee, h);

        dim3 g1((4 * Ee) / BN, MBT / BM);
        gemm_kernel<true, EPI_BIASRELU, false><<<g1, 256>>>(h, W1 + (long long)l * 4 * Ee * Ee, u,
            MBT, 4 * Ee, Ee, 0, 0, 0, b1 + l * 4 * Ee, nullptr);

        dim3 g2(Ee / BN, MBT / BM);
        gemm_kernel<true, EPI_BIASRES, false><<<g2, 256>>>(u, W2 + (long long)l * Ee * 4 * Ee, y,
            MBT, Ee, 4 * Ee, 0, 0, 0, b2 + l * Ee, h);
    }

    logits_kernel<<<MBT / 8, 256>>>(y, Wout, bout, out);
}

// round 3
// speedup vs baseline: 2.9465x; 2.9465x over previous
#include <cuda_runtime.h>
#include <cuda_bf16.h>
#include <cstdint>

// ---------------- problem constants ----------------
#define Bb 4
#define Tt 2048
#define Ee 512
#define Hh 8
#define Ll 5
#define Vv 130
#define Dd 512
#define TD (Tt * Dd)
#define TT (Tt * Tt)

// ---------------- device scratch ----------------
__device__ float g_y[Bb * Tt * Ee];
__device__ float g_h[Bb * Tt * Ee];
__device__ float g_q[Bb * Hh * Tt * Dd];
__device__ float g_k[Bb * Hh * Tt * Dd];
__device__ float g_v[Bb * Hh * Tt * Dd];
__device__ float g_s[(long long)Bb * Hh * Tt * Tt];
__device__ float g_ao[Bb * Hh * Tt * Dd];
__device__ float g_u[Bb * Tt * 4 * Ee];

// ---------------- tf32 tensor-core GEMM ----------------
constexpr int BM = 128, BN = 128, BK = 16;
constexpr int APAD = 20;        // row stride (floats) for [row][k] tiles; 80B = 16B aligned, conflict-free
constexpr int BPAD_NN = 136;    // row stride for NN B tile [k][n]; 544B aligned, conflict-free frag loads
constexpr int ASZ = 2 * BM * APAD;
constexpr int BSZ_NT = 2 * BN * APAD;
constexpr int BSZ_NN = 2 * BK * BPAD_NN;

enum { EPI_PLAIN = 0, EPI_QKV = 1, EPI_CAUSAL = 2, EPI_BIASRELU = 3, EPI_BIASRES = 4 };

__device__ __forceinline__ uint32_t f2tf32(float x) {
    uint32_t u;
    asm("cvt.rna.tf32.f32 %0, %1;" : "=r"(u) : "f"(x));
    return u;
}
__device__ __forceinline__ void cpa16(uint32_t s, const void* g) {
    asm volatile("cp.async.cg.shared.global [%0], [%1], 16;" :: "r"(s), "l"(g));
}

template <int EPI>
__device__ __forceinline__ void store_pair(float* __restrict__ C, const float* __restrict__ bias,
                                           const float* __restrict__ Res, int N,
                                           int m, int n, float v0, float v1)
{
    if (EPI == EPI_PLAIN) {
        *reinterpret_cast<float2*>(&C[(long long)m * N + n]) = make_float2(v0, v1);
    } else if (EPI == EPI_QKV) {
        const int b_ = m >> 11, t = m & (Tt - 1);
        const int h = n >> 9, d = n & (Dd - 1);
        *reinterpret_cast<float2*>(&C[((long long)(b_ * Hh + h) << 20) + ((long long)t << 9) + d]) =
            make_float2(v0, v1);
    } else if (EPI == EPI_CAUSAL) {
        v0 *= 0.044194173824159216f;
        v1 *= 0.044194173824159216f;
        if (n > m)     v0 = -1e30f;
        if (n + 1 > m) v1 = -1e30f;
        *reinterpret_cast<float2*>(&C[(long long)m * N + n]) = make_float2(v0, v1);
    } else if (EPI == EPI_BIASRELU) {
        v0 = fmaxf(v0 + bias[n], 0.f);
        v1 = fmaxf(v1 + bias[n + 1], 0.f);
        *reinterpret_cast<float2*>(&C[(long long)m * N + n]) = make_float2(v0, v1);
    } else {  // EPI_BIASRES
        const float2 r = *reinterpret_cast<const float2*>(&Res[(long long)m * N + n]);
        v0 += bias[n] + r.x;
        v1 += bias[n + 1] + r.y;
        *reinterpret_cast<float2*>(&C[(long long)m * N + n]) = make_float2(v0, v1);
    }
}

// C = A * op(B); A row-major [M,K]; BNT: B row-major [N,K] (NT) else [K,N] (NN)
template <bool BNT, int EPI, bool CK>
__global__ __launch_bounds__(256) void gemm_tc(
    const float* __restrict__ A, const float* __restrict__ B, float* __restrict__ C,
    int M, int N, int K,
    long long sA_, long long sB_, long long sC_,
    const float* __restrict__ bias, const float* __restrict__ Res)
{
    const int bx = blockIdx.x, by = blockIdx.y, bz = blockIdx.z;
    if (EPI == EPI_CAUSAL && bx > by) return;  // skip strictly-upper tiles

    A += (long long)bz * sA_;
    B += (long long)bz * sB_;
    C += (long long)bz * sC_;

    int Keff = K;
    if (CK) { int ke = (by + 1) * BM; Keff = ke < K ? ke : K; }
    const int NTILES = Keff / BK;

    __shared__ float smem[ASZ + (BNT ? BSZ_NT : BSZ_NN)];
    float* sA = smem;
    float* sB = smem + ASZ;

    const int tid = threadIdx.x;
    const int wid = tid >> 5, lane = tid & 31;
    const int g = lane >> 2, tig = lane & 3;   // mma fragment coords
    const int wm = wid & 1, wn = wid >> 1;     // 2x4 warp grid; warp tile 64x32
    const int m0 = by * BM, n0 = bx * BN;

    // loader indices
    const int ar = tid >> 2, ac = (tid & 3) << 2;   // A / B(NT): rows 0..63 (+64), cols {0,4,8,12}
    const int br = tid >> 5, bc = (tid & 31) << 2;  // B(NN): k-rows 0..7 (+8), cols 0..124

    float c[4][4][4];
#pragma unroll
    for (int i = 0; i < 4; i++)
#pragma unroll
        for (int j = 0; j < 4; j++)
#pragma unroll
            for (int q = 0; q < 4; q++) c[i][j][q] = 0.f;

    auto loadTiles = [&](int st, int kt) {
        const int k0 = kt * BK;
#pragma unroll
        for (int r = 0; r < BM; r += 64) {
            uint32_t d = (uint32_t)__cvta_generic_to_shared(&sA[st * BM * APAD + (ar + r) * APAD + ac]);
            cpa16(d, &A[(long long)(m0 + ar + r) * K + k0 + ac]);
        }
        if (BNT) {
#pragma unroll
            for (int r = 0; r < BN; r += 64) {
                uint32_t d = (uint32_t)__cvta_generic_to_shared(&sB[st * BN * APAD + (ar + r) * APAD + ac]);
                cpa16(d, &B[(long long)(n0 + ar + r) * K + k0 + ac]);
            }
        } else {
#pragma unroll
            for (int r = 0; r < BK; r += 8) {
                uint32_t d = (uint32_t)__cvta_generic_to_shared(&sB[st * BK * BPAD_NN + (br + r) * BPAD_NN + bc]);
                cpa16(d, &B[(long long)(k0 + br + r) * N + n0 + bc]);
            }
        }
    };

    loadTiles(0, 0);
    asm volatile("cp.async.commit_group;");

    int st = 0;
    for (int it = 0; it < NTILES; ++it) {
        if (it + 1 < NTILES) {
            loadTiles(st ^ 1, it + 1);
            asm volatile("cp.async.commit_group;");
            asm volatile("cp.async.wait_group 1;");
        } else {
            asm volatile("cp.async.wait_group 0;");
        }
        __syncthreads();

#pragma unroll
        for (int k0 = 0; k0 < BK; k0 += 8) {
            uint32_t af[4][4], bf[4][2];
#pragma unroll
            for (int mt = 0; mt < 4; mt++) {
                const float* base = &sA[st * BM * APAD + (wm * 64 + mt * 16 + g) * APAD + k0 + tig];
                af[mt][0] = f2tf32(base[0]);            // (g,     tig)
                af[mt][1] = f2tf32(base[8 * APAD]);     // (g+8,   tig)
                af[mt][2] = f2tf32(base[4]);            // (g,     tig+4)
                af[mt][3] = f2tf32(base[8 * APAD + 4]); // (g+8,   tig+4)
            }
#pragma unroll
            for (int nt = 0; nt < 4; nt++) {
                if (BNT) {
                    const float* base = &sB[st * BN * APAD + (wn * 32 + nt * 8 + g) * APAD + k0 + tig];
                    bf[nt][0] = f2tf32(base[0]);        // B[n][k=tig]
                    bf[nt][1] = f2tf32(base[4]);        // B[n][k=tig+4]
                } else {
                    const float* base = &sB[st * BK * BPAD_NN + (k0 + tig) * BPAD_NN + wn * 32 + nt * 8 + g];
                    bf[nt][0] = f2tf32(base[0]);            // B[k=tig][n]
                    bf[nt][1] = f2tf32(base[4 * BPAD_NN]);  // B[k=tig+4][n]
                }
            }
#pragma unroll
            for (int mt = 0; mt < 4; mt++)
#pragma unroll
                for (int nt = 0; nt < 4; nt++) {
                    asm volatile(
                        "mma.sync.aligned.m16n8k8.row.col.f32.tf32.tf32.f32 "
                        "{%0,%1,%2,%3}, {%4,%5,%6,%7}, {%8,%9}, {%0,%1,%2,%3};"
                        : "+f"(c[mt][nt][0]), "+f"(c[mt][nt][1]),
                          "+f"(c[mt][nt][2]), "+f"(c[mt][nt][3])
                        : "r"(af[mt][0]), "r"(af[mt][1]), "r"(af[mt][2]), "r"(af[mt][3]),
                          "r"(bf[nt][0]), "r"(bf[nt][1]));
                }
        }
        __syncthreads();
        st ^= 1;
    }

    // epilogue: c0,c1 -> row g cols 2tig,2tig+1 ; c2,c3 -> row g+8
#pragma unroll
    for (int mt = 0; mt < 4; mt++) {
        const int mrow = m0 + wm * 64 + mt * 16 + g;
#pragma unroll
        for (int nt = 0; nt < 4; nt++) {
            const int ncol = n0 + wn * 32 + nt * 8 + tig * 2;
            store_pair<EPI>(C, bias, Res, N, mrow,     ncol, c[mt][nt][0], c[mt][nt][1]);
            store_pair<EPI>(C, bias, Res, N, mrow + 8, ncol, c[mt][nt][2], c[mt][nt][3]);
        }
    }
}

// ---------------- LayerNorm ----------------
__global__ void ln_kernel(const float* __restrict__ x, const float* __restrict__ g,
                          const float* __restrict__ b, float* __restrict__ out)
{
    const int row = blockIdx.x;
    const float* xr = x + (long long)row * Ee;
    const int tid = threadIdx.x;  // 256
    float v0 = xr[tid], v1 = xr[tid + 256];
    float s = v0 + v1, sq = v0 * v0 + v1 * v1;
#pragma unroll
    for (int o = 16; o; o >>= 1) {
        s  += __shfl_xor_sync(0xffffffffu, s,  o);
        sq += __shfl_xor_sync(0xffffffffu, sq, o);
    }
    __shared__ float ss[8], sqq[8];
    const int warp = tid >> 5, lane = tid & 31;
    if (lane == 0) { ss[warp] = s; sqq[warp] = sq; }
    __syncthreads();
    if (tid == 0) {
        float a = 0.f, c2 = 0.f;
#pragma unroll
        for (int i = 0; i < 8; i++) { a += ss[i]; c2 += sqq[i]; }
        ss[0] = a; sqq[0] = c2;
    }
    __syncthreads();
    const float mu  = ss[0] * (1.f / 512.f);
    const float var = sqq[0] * (1.f / 512.f) - mu * mu;
    const float r = rsqrtf(var + 1e-5f);
    out[(long long)row * Ee + tid]       = (v0 - mu) * r * g[tid]       + b[tid];
    out[(long long)row * Ee + tid + 256] = (v1 - mu) * r * g[tid + 256] + b[tid + 256];
}

// ---------------- causal softmax: one block (256 thr) per row, float4 ----------------
__global__ void softmax_kernel(float* __restrict__ S)
{
    const long long r = blockIdx.x;
    const int t = (int)(r & (Tt - 1));
    float* row = S + (r << 11);
    const int len4 = (((t >> 7) + 1) << 7) >> 2;
    const int tid = threadIdx.x;  // 256

    float4 e[2];
    float mx = -1e30f;
#pragma unroll
    for (int c = 0; c < 2; c++) {
        const int i = tid + c * 256;
        if (i < len4) {
            e[c] = *reinterpret_cast<const float4*>(&row[i << 2]);
            mx = fmaxf(fmaxf(fmaxf(e[c].x, e[c].y), fmaxf(e[c].z, e[c].w)), mx);
        }
    }
    __shared__ float redmax[8], redsum[8];
#pragma unroll
    for (int o = 16; o; o >>= 1) mx = fmaxf(mx, __shfl_xor_sync(0xffffffffu, mx, o));
    const int warp = tid >> 5, lane = tid & 31;
    if (lane == 0) redmax[warp] = mx;
    __syncthreads();
    mx = redmax[0];
#pragma unroll
    for (int w = 1; w < 8; w++) mx = fmaxf(mx, redmax[w]);

    float sum = 0.f;
#pragma unroll
    for (int c = 0; c < 2; c++) {
        const int i = tid + c * 256;
        if (i < len4) {
            e[c].x = expf(e[c].x - mx); e[c].y = expf(e[c].y - mx);
            e[c].z = expf(e[c].z - mx); e[c].w = expf(e[c].w - mx);
            sum += (e[c].x + e[c].y) + (e[c].z + e[c].w);
        }
    }
#pragma unroll
    for (int o = 16; o; o >>= 1) sum += __shfl_xor_sync(0xffffffffu, sum, o);
    if (lane == 0) redsum[warp] = sum;
    __syncthreads();
    sum = 0.f;
#pragma unroll
    for (int w = 0; w < 8; w++) sum += redsum[w];
    const float inv = 1.f / sum;
#pragma unroll
    for (int c = 0; c < 2; c++) {
        const int i = tid + c * 256;
        if (i < len4) {
            e[c].x *= inv; e[c].y *= inv; e[c].z *= inv; e[c].w *= inv;
            *reinterpret_cast<float4*>(&row[i << 2]) = e[c];
        }
    }
}

// ---------------- embedding ----------------
__global__ void embed_kernel(const int* __restrict__ tokens, const float* __restrict__ emb,
                             const float* __restrict__ pos, float* __restrict__ y)
{
    const long long idx = (long long)blockIdx.x * 256 + threadIdx.x;
    const int e = (int)(idx & (Ee - 1));
    const long long m = idx >> 9;
    const int t = (int)(m & (Tt - 1));
    const int tok = tokens[m];
    y[idx] = emb[(long long)tok * Ee + e] + pos[(long long)t * Ee + e];
}

// ---------------- head sum + residual (float4) ----------------
__global__ void headsum_kernel(const float* __restrict__ ao, float* __restrict__ y)
{
    const long long i4 = (long long)blockIdx.x * 256 + threadIdx.x;
    const long long idx = i4 << 2;
    const int e = (int)(idx & (Ee - 1));
    const long long m = idx >> 9;
    const int b_ = (int)(m >> 11);
    const int t = (int)(m & (Tt - 1));
    float4 s = *reinterpret_cast<const float4*>(&y[idx]);
    const long long base = ((long long)(b_ * Hh) << 20) + ((long long)t << 9) + e;
#pragma unroll
    for (int h = 0; h < Hh; h++) {
        float4 a = *reinterpret_cast<const float4*>(&ao[base + ((long long)h << 20)]);
        s.x += a.x; s.y += a.y; s.z += a.z; s.w += a.w;
    }
    *reinterpret_cast<float4*>(&y[idx]) = s;
}

// ---------------- logits: warp per row, N=130 ----------------
__global__ void logits_kernel(const float* __restrict__ y, const float* __restrict__ Wout,
                              const float* __restrict__ bout, float* __restrict__ out)
{
    const int warp = threadIdx.x >> 5, lane = threadIdx.x & 31;
    const int m = blockIdx.x * 8 + warp;
    const float* yr = y + (long long)m * Ee;
    float yreg[16];
#pragma unroll
    for (int i = 0; i < 16; i++) yreg[i] = yr[lane + i * 32];
    for (int n = 0; n < Vv; n++) {
        const float* w = Wout + (long long)n * Ee;
        float s = 0.f;
#pragma unroll
        for (int i = 0; i < 16; i++) s = fmaf(yreg[i], w[lane + i * 32], s);
#pragma unroll
        for (int o = 16; o; o >>= 1) s += __shfl_xor_sync(0xffffffffu, s, o);
        if (lane == 0) out[(long long)m * Vv + n] = s + bout[n];
    }
}

// ---------------- driver ----------------
extern "C" void kernel_launch(void* const* d_in, const int* in_sizes, int n_in,
                              void* d_out, int out_size)
{
    const int*   tokens = (const int*)  d_in[0];
    const float* emb    = (const float*)d_in[1];
    const float* pos    = (const float*)d_in[2];
    const float* ln1_g  = (const float*)d_in[3];
    const float* ln1_b  = (const float*)d_in[4];
    const float* Wq     = (const float*)d_in[5];
    const float* Wk     = (const float*)d_in[6];
    const float* Wv     = (const float*)d_in[7];
    const float* ln2_g  = (const float*)d_in[8];
    const float* ln2_b  = (const float*)d_in[9];
    const float* W1     = (const float*)d_in[10];
    const float* b1     = (const float*)d_in[11];
    const float* W2     = (const float*)d_in[12];
    const float* b2     = (const float*)d_in[13];
    const float* Wout   = (const float*)d_in[14];
    const float* bout   = (const float*)d_in[15];
    float* out = (float*)d_out;

    float *y, *h, *q, *k, *v, *s, *ao, *u;
    cudaGetSymbolAddress((void**)&y,  g_y);
    cudaGetSymbolAddress((void**)&h,  g_h);
    cudaGetSymbolAddress((void**)&q,  g_q);
    cudaGetSymbolAddress((void**)&k,  g_k);
    cudaGetSymbolAddress((void**)&v,  g_v);
    cudaGetSymbolAddress((void**)&s,  g_s);
    cudaGetSymbolAddress((void**)&ao, g_ao);
    cudaGetSymbolAddress((void**)&u,  g_u);

    const int MBT = Bb * Tt;  // 8192
    const long long WqkvStride = (long long)Hh * Dd * Ee;

    embed_kernel<<<(MBT * Ee) / 256, 256>>>(tokens, emb, pos, y);

    for (int l = 0; l < Ll; l++) {
        ln_kernel<<<MBT, 256>>>(y, ln1_g + l * Ee, ln1_b + l * Ee, h);

        dim3 gqkv(4096 / BN, MBT / BM);
        gemm_tc<true, EPI_QKV, false><<<gqkv, 256>>>(h, Wq + l * WqkvStride, q,
            MBT, Hh * Dd, Ee, 0, 0, 0, nullptr, nullptr);
        gemm_tc<true, EPI_QKV, false><<<gqkv, 256>>>(h, Wk + l * WqkvStride, k,
            MBT, Hh * Dd, Ee, 0, 0, 0, nullptr, nullptr);
        gemm_tc<true, EPI_QKV, false><<<gqkv, 256>>>(h, Wv + l * WqkvStride, v,
            MBT, Hh * Dd, Ee, 0, 0, 0, nullptr, nullptr);

        dim3 gqk(Tt / BN, Tt / BM, Bb * Hh);
        gemm_tc<true, EPI_CAUSAL, false><<<gqk, 256>>>(q, k, s,
            Tt, Tt, Dd, (long long)TD, (long long)TD, (long long)TT, nullptr, nullptr);

        softmax_kernel<<<Bb * Hh * Tt, 256>>>(s);

        dim3 gav(Dd / BN, Tt / BM, Bb * Hh);
        gemm_tc<false, EPI_PLAIN, true><<<gav, 256>>>(s, v, ao,
            Tt, Dd, Tt, (long long)TT, (long long)TD, (long long)TD, nullptr, nullptr);

        headsum_kernel<<<(MBT * Ee) / 1024, 256>>>(ao, y);

        ln_kernel<<<MBT, 256>>>(y, ln2_g + l * Ee, ln2_b + l * Ee, h);

        dim3 g1((4 * Ee) / BN, MBT / BM);
        gemm_tc<true, EPI_BIASRELU, false><<<g1, 256>>>(h, W1 + (long long)l * 4 * Ee * Ee, u,
            MBT, 4 * Ee, Ee, 0, 0, 0, b1 + l * 4 * Ee, nullptr);

        dim3 g2(Ee / BN, MBT / BM);
        gemm_tc<true, EPI_BIASRES, false><<<g2, 256>>>(u, W2 + (long long)l * Ee * 4 * Ee, y,
            MBT, Ee, 4 * Ee, 0, 0, 0, b2 + l * Ee, h);
    }

    logits_kernel<<<MBT / 8, 256>>>(y, Wout, bout, out);
}

// round 5
// speedup vs baseline: 2.9798x; 1.0113x over previous
#include <cuda_runtime.h>
#include <cuda_bf16.h>
#include <cstdint>

// ---------------- problem constants ----------------
#define Bb 4
#define Tt 2048
#define Ee 512
#define Hh 8
#define Ll 5
#define Vv 130
#define Dd 512
#define TD (Tt * Dd)
#define TT (Tt * Tt)

// ---------------- device scratch ----------------
__device__ float g_y[Bb * Tt * Ee];                  // residual stream (fp32)
__device__ float g_h[Bb * Tt * Ee];                  // LN output fp32 (residual source)
__device__ float g_htf[Bb * Tt * Ee];                // LN output tf32 (GEMM A operand)
__device__ float g_q[Bb * Hh * Tt * Dd];             // tf32
__device__ float g_k[Bb * Hh * Tt * Dd];             // tf32
__device__ float g_v[Bb * Hh * Tt * Dd];             // tf32
__device__ float g_s[(long long)Bb * Hh * Tt * Tt];  // scores; tf32 after softmax
__device__ float g_ao[Bb * Hh * Tt * Dd];            // fp32 per-head attn out
__device__ float g_u[Bb * Tt * 4 * Ee];              // MLP hidden, tf32
// pre-converted tf32 weights
__device__ float g_wq[Ll * Hh * Dd * Ee];
__device__ float g_wk[Ll * Hh * Dd * Ee];
__device__ float g_wv[Ll * Hh * Dd * Ee];
__device__ float g_w1[Ll * 4 * Ee * Ee];
__device__ float g_w2[Ll * 4 * Ee * Ee];

// ---------------- tf32 helpers ----------------
__device__ __forceinline__ uint32_t f2tf32(float x) {
    uint32_t u;
    asm("cvt.rna.tf32.f32 %0, %1;" : "=r"(u) : "f"(x));
    return u;
}
__device__ __forceinline__ float f2tf32f(float x) { return __uint_as_float(f2tf32(x)); }
__device__ __forceinline__ void cpa16(uint32_t s, const void* g) {
    asm volatile("cp.async.cg.shared.global [%0], [%1], 16;" :: "r"(s), "l"(g));
}

// ---------------- weight pre-conversion (fp32 -> tf32 bits) ----------------
__global__ void cvtw_kernel(const float* __restrict__ src, float* __restrict__ dst)
{
    const long long i = ((long long)blockIdx.x * 256 + threadIdx.x) << 2;
    float4 v = *reinterpret_cast<const float4*>(&src[i]);
    v.x = f2tf32f(v.x); v.y = f2tf32f(v.y); v.z = f2tf32f(v.z); v.w = f2tf32f(v.w);
    *reinterpret_cast<float4*>(&dst[i]) = v;
}

// ---------------- tf32 tensor-core GEMM ----------------
constexpr int BM = 128, BN = 128, BK = 16;
constexpr int APAD = 20;
constexpr int BPAD_NN = 136;
constexpr int ASZ = 2 * BM * APAD;
constexpr int BSZ_NT = 2 * BN * APAD;
constexpr int BSZ_NN = 2 * BK * BPAD_NN;

enum { EPI_PLAIN = 0, EPI_QKV = 1, EPI_CAUSAL = 2, EPI_BIASRELU = 3, EPI_BIASRES = 4 };

template <int EPI>
__device__ __forceinline__ void store_pair(float* __restrict__ C, const float* __restrict__ bias,
                                           const float* __restrict__ Res, int N,
                                           int m, int n, float v0, float v1)
{
    if (EPI == EPI_PLAIN) {
        *reinterpret_cast<float2*>(&C[(long long)m * N + n]) = make_float2(v0, v1);
    } else if (EPI == EPI_QKV) {
        const int b_ = m >> 11, t = m & (Tt - 1);
        const int h = n >> 9, d = n & (Dd - 1);
        // q/k/v are GEMM operands downstream -> store tf32-rounded
        *reinterpret_cast<float2*>(&C[((long long)(b_ * Hh + h) << 20) + ((long long)t << 9) + d]) =
            make_float2(f2tf32f(v0), f2tf32f(v1));
    } else if (EPI == EPI_CAUSAL) {
        v0 *= 0.044194173824159216f;
        v1 *= 0.044194173824159216f;
        if (n > m)     v0 = -1e30f;
        if (n + 1 > m) v1 = -1e30f;
        *reinterpret_cast<float2*>(&C[(long long)m * N + n]) = make_float2(v0, v1);
    } else if (EPI == EPI_BIASRELU) {
        // u feeds MLP2 GEMM -> tf32-rounded
        v0 = f2tf32f(fmaxf(v0 + bias[n], 0.f));
        v1 = f2tf32f(fmaxf(v1 + bias[n + 1], 0.f));
        *reinterpret_cast<float2*>(&C[(long long)m * N + n]) = make_float2(v0, v1);
    } else {  // EPI_BIASRES: full fp32 residual
        const float2 r = *reinterpret_cast<const float2*>(&Res[(long long)m * N + n]);
        v0 += bias[n] + r.x;
        v1 += bias[n + 1] + r.y;
        *reinterpret_cast<float2*>(&C[(long long)m * N + n]) = make_float2(v0, v1);
    }
}

// C = A * op(B); A row-major [M,K]; BNT: B row-major [N,K] (NT) else [K,N] (NN)
// All A/B inputs are ALREADY tf32-rounded fp32 bit patterns.
template <bool BNT, int EPI, bool CK>
__global__ __launch_bounds__(256) void gemm_tc(
    const float* __restrict__ A, const float* __restrict__ B, float* __restrict__ C,
    int M, int N, int K,
    long long sA_, long long sB_, long long sC_,
    const float* __restrict__ bias, const float* __restrict__ Res)
{
    const int bx = blockIdx.x, by = blockIdx.y, bz = blockIdx.z;
    if (EPI == EPI_CAUSAL && bx > by) return;

    A += (long long)bz * sA_;
    B += (long long)bz * sB_;
    C += (long long)bz * sC_;

    int Keff = K;
    if (CK) { int ke = (by + 1) * BM; Keff = ke < K ? ke : K; }
    const int NTILES = Keff / BK;

    __shared__ float smem[ASZ + (BNT ? BSZ_NT : BSZ_NN)];
    float* sA = smem;
    float* sB = smem + ASZ;

    const int tid = threadIdx.x;
    const int wid = tid >> 5, lane = tid & 31;
    const int g = lane >> 2, tig = lane & 3;
    const int wm = wid & 1, wn = wid >> 1;     // 2x4 warp grid; warp tile 64x32
    const int m0 = by * BM, n0 = bx * BN;

    const int ar = tid >> 2, ac = (tid & 3) << 2;
    const int br = tid >> 5, bc = (tid & 31) << 2;

    float c[4][4][4];
#pragma unroll
    for (int i = 0; i < 4; i++)
#pragma unroll
        for (int j = 0; j < 4; j++)
#pragma unroll
            for (int q = 0; q < 4; q++) c[i][j][q] = 0.f;

    auto loadTiles = [&](int st, int kt) {
        const int k0 = kt * BK;
#pragma unroll
        for (int r = 0; r < BM; r += 64) {
            uint32_t d = (uint32_t)__cvta_generic_to_shared(&sA[st * BM * APAD + (ar + r) * APAD + ac]);
            cpa16(d, &A[(long long)(m0 + ar + r) * K + k0 + ac]);
        }
        if (BNT) {
#pragma unroll
            for (int r = 0; r < BN; r += 64) {
                uint32_t d = (uint32_t)__cvta_generic_to_shared(&sB[st * BN * APAD + (ar + r) * APAD + ac]);
                cpa16(d, &B[(long long)(n0 + ar + r) * K + k0 + ac]);
            }
        } else {
#pragma unroll
            for (int r = 0; r < BK; r += 8) {
                uint32_t d = (uint32_t)__cvta_generic_to_shared(&sB[st * BK * BPAD_NN + (br + r) * BPAD_NN + bc]);
                cpa16(d, &B[(long long)(k0 + br + r) * N + n0 + bc]);
            }
        }
    };

    loadTiles(0, 0);
    asm volatile("cp.async.commit_group;");

    int st = 0;
    for (int it = 0; it < NTILES; ++it) {
        if (it + 1 < NTILES) {
            loadTiles(st ^ 1, it + 1);
            asm volatile("cp.async.commit_group;");
            asm volatile("cp.async.wait_group 1;");
        } else {
            asm volatile("cp.async.wait_group 0;");
        }
        __syncthreads();

#pragma unroll
        for (int k0 = 0; k0 < BK; k0 += 8) {
            uint32_t af[4][4], bf[4][2];
#pragma unroll
            for (int mt = 0; mt < 4; mt++) {
                const uint32_t* base = reinterpret_cast<const uint32_t*>(
                    &sA[st * BM * APAD + (wm * 64 + mt * 16 + g) * APAD + k0 + tig]);
                af[mt][0] = base[0];
                af[mt][1] = base[8 * APAD];
                af[mt][2] = base[4];
                af[mt][3] = base[8 * APAD + 4];
            }
#pragma unroll
            for (int nt = 0; nt < 4; nt++) {
                if (BNT) {
                    const uint32_t* base = reinterpret_cast<const uint32_t*>(
                        &sB[st * BN * APAD + (wn * 32 + nt * 8 + g) * APAD + k0 + tig]);
                    bf[nt][0] = base[0];
                    bf[nt][1] = base[4];
                } else {
                    const uint32_t* base = reinterpret_cast<const uint32_t*>(
                        &sB[st * BK * BPAD_NN + (k0 + tig) * BPAD_NN + wn * 32 + nt * 8 + g]);
                    bf[nt][0] = base[0];
                    bf[nt][1] = base[4 * BPAD_NN];
                }
            }
#pragma unroll
            for (int mt = 0; mt < 4; mt++)
#pragma unroll
                for (int nt = 0; nt < 4; nt++) {
                    asm volatile(
                        "mma.sync.aligned.m16n8k8.row.col.f32.tf32.tf32.f32 "
                        "{%0,%1,%2,%3}, {%4,%5,%6,%7}, {%8,%9}, {%0,%1,%2,%3};"
                        : "+f"(c[mt][nt][0]), "+f"(c[mt][nt][1]),
                          "+f"(c[mt][nt][2]), "+f"(c[mt][nt][3])
                        : "r"(af[mt][0]), "r"(af[mt][1]), "r"(af[mt][2]), "r"(af[mt][3]),
                          "r"(bf[nt][0]), "r"(bf[nt][1]));
                }
        }
        __syncthreads();
        st ^= 1;
    }

#pragma unroll
    for (int mt = 0; mt < 4; mt++) {
        const int mrow = m0 + wm * 64 + mt * 16 + g;
#pragma unroll
        for (int nt = 0; nt < 4; nt++) {
            const int ncol = n0 + wn * 32 + nt * 8 + tig * 2;
            store_pair<EPI>(C, bias, Res, N, mrow,     ncol, c[mt][nt][0], c[mt][nt][1]);
            store_pair<EPI>(C, bias, Res, N, mrow + 8, ncol, c[mt][nt][2], c[mt][nt][3]);
        }
    }
}

// ---------------- LayerNorm: writes fp32 copy (residual) + tf32 copy (GEMM A) ----------------
__global__ void ln_kernel(const float* __restrict__ x, const float* __restrict__ g,
                          const float* __restrict__ b, float* __restrict__ out,
                          float* __restrict__ out_tf)
{
    const int row = blockIdx.x;
    const float* xr = x + (long long)row * Ee;
    const int tid = threadIdx.x;  // 256
    float v0 = xr[tid], v1 = xr[tid + 256];
    float s = v0 + v1, sq = v0 * v0 + v1 * v1;
#pragma unroll
    for (int o = 16; o; o >>= 1) {
        s  += __shfl_xor_sync(0xffffffffu, s,  o);
        sq += __shfl_xor_sync(0xffffffffu, sq, o);
    }
    __shared__ float ss[8], sqq[8];
    const int warp = tid >> 5, lane = tid & 31;
    if (lane == 0) { ss[warp] = s; sqq[warp] = sq; }
    __syncthreads();
    if (tid == 0) {
        float a = 0.f, c2 = 0.f;
#pragma unroll
        for (int i = 0; i < 8; i++) { a += ss[i]; c2 += sqq[i]; }
        ss[0] = a; sqq[0] = c2;
    }
    __syncthreads();
    const float mu  = ss[0] * (1.f / 512.f);
    const float var = sqq[0] * (1.f / 512.f) - mu * mu;
    const float r = rsqrtf(var + 1e-5f);
    const float o0 = (v0 - mu) * r * g[tid]       + b[tid];
    const float o1 = (v1 - mu) * r * g[tid + 256] + b[tid + 256];
    out[(long long)row * Ee + tid]          = o0;
    out[(long long)row * Ee + tid + 256]    = o1;
    out_tf[(long long)row * Ee + tid]       = f2tf32f(o0);
    out_tf[(long long)row * Ee + tid + 256] = f2tf32f(o1);
}

// ---------------- causal softmax: stores tf32-rounded probabilities ----------------
__global__ void softmax_kernel(float* __restrict__ S)
{
    const long long r = blockIdx.x;
    const int t = (int)(r & (Tt - 1));
    float* row = S + (r << 11);
    const int len4 = (((t >> 7) + 1) << 7) >> 2;
    const int tid = threadIdx.x;  // 256

    float4 e[2];
    float mx = -1e30f;
#pragma unroll
    for (int c = 0; c < 2; c++) {
        const int i = tid + c * 256;
        if (i < len4) {
            e[c] = *reinterpret_cast<const float4*>(&row[i << 2]);
            mx = fmaxf(fmaxf(fmaxf(e[c].x, e[c].y), fmaxf(e[c].z, e[c].w)), mx);
        }
    }
    __shared__ float redmax[8], redsum[8];
#pragma unroll
    for (int o = 16; o; o >>= 1) mx = fmaxf(mx, __shfl_xor_sync(0xffffffffu, mx, o));
    const int warp = tid >> 5, lane = tid & 31;
    if (lane == 0) redmax[warp] = mx;
    __syncthreads();
    mx = redmax[0];
#pragma unroll
    for (int w = 1; w < 8; w++) mx = fmaxf(mx, redmax[w]);

    float sum = 0.f;
#pragma unroll
    for (int c = 0; c < 2; c++) {
        const int i = tid + c * 256;
        if (i < len4) {
            e[c].x = expf(e[c].x - mx); e[c].y = expf(e[c].y - mx);
            e[c].z = expf(e[c].z - mx); e[c].w = expf(e[c].w - mx);
            sum += (e[c].x + e[c].y) + (e[c].z + e[c].w);
        }
    }
#pragma unroll
    for (int o = 16; o; o >>= 1) sum += __shfl_xor_sync(0xffffffffu, sum, o);
    if (lane == 0) redsum[warp] = sum;
    __syncthreads();
    sum = 0.f;
#pragma unroll
    for (int w = 0; w < 8; w++) sum += redsum[w];
    const float inv = 1.f / sum;
#pragma unroll
    for (int c = 0; c < 2; c++) {
        const int i = tid + c * 256;
        if (i < len4) {
            e[c].x = f2tf32f(e[c].x * inv); e[c].y = f2tf32f(e[c].y * inv);
            e[c].z = f2tf32f(e[c].z * inv); e[c].w = f2tf32f(e[c].w * inv);
            *reinterpret_cast<float4*>(&row[i << 2]) = e[c];
        }
    }
}

// ---------------- embedding ----------------
__global__ void embed_kernel(const int* __restrict__ tokens, const float* __restrict__ emb,
                             const float* __restrict__ pos, float* __restrict__ y)
{
    const long long idx = (long long)blockIdx.x * 256 + threadIdx.x;
    const int e = (int)(idx & (Ee - 1));
    const long long m = idx >> 9;
    const int t = (int)(m & (Tt - 1));
    const int tok = tokens[m];
    y[idx] = emb[(long long)tok * Ee + e] + pos[(long long)t * Ee + e];
}

// ---------------- head sum + residual (float4) ----------------
__global__ void headsum_kernel(const float* __restrict__ ao, float* __restrict__ y)
{
    const long long i4 = (long long)blockIdx.x * 256 + threadIdx.x;
    const long long idx = i4 << 2;
    const int e = (int)(idx & (Ee - 1));
    const long long m = idx >> 9;
    const int b_ = (int)(m >> 11);
    const int t = (int)(m & (Tt - 1));
    float4 s = *reinterpret_cast<const float4*>(&y[idx]);
    const long long base = ((long long)(b_ * Hh) << 20) + ((long long)t << 9) + e;
#pragma unroll
    for (int h = 0; h < Hh; h++) {
        float4 a = *reinterpret_cast<const float4*>(&ao[base + ((long long)h << 20)]);
        s.x += a.x; s.y += a.y; s.z += a.z; s.w += a.w;
    }
    *reinterpret_cast<float4*>(&y[idx]) = s;
}

// ---------------- logits: warp per row, N=130 ----------------
__global__ void logits_kernel(const float* __restrict__ y, const float* __restrict__ Wout,
                              const float* __restrict__ bout, float* __restrict__ out)
{
    const int warp = threadIdx.x >> 5, lane = threadIdx.x & 31;
    const int m = blockIdx.x * 8 + warp;
    const float* yr = y + (long long)m * Ee;
    float yreg[16];
#pragma unroll
    for (int i = 0; i < 16; i++) yreg[i] = yr[lane + i * 32];
    for (int n = 0; n < Vv; n++) {
        const float* w = Wout + (long long)n * Ee;
        float s = 0.f;
#pragma unroll
        for (int i = 0; i < 16; i++) s = fmaf(yreg[i], w[lane + i * 32], s);
#pragma unroll
        for (int o = 16; o; o >>= 1) s += __shfl_xor_sync(0xffffffffu, s, o);
        if (lane == 0) out[(long long)m * Vv + n] = s + bout[n];
    }
}

// ---------------- driver ----------------
extern "C" void kernel_launch(void* const* d_in, const int* in_sizes, int n_in,
                              void* d_out, int out_size)
{
    const int*   tokens = (const int*)  d_in[0];
    const float* emb    = (const float*)d_in[1];
    const float* pos    = (const float*)d_in[2];
    const float* ln1_g  = (const float*)d_in[3];
    const float* ln1_b  = (const float*)d_in[4];
    const float* Wq     = (const float*)d_in[5];
    const float* Wk     = (const float*)d_in[6];
    const float* Wv     = (const float*)d_in[7];
    const float* ln2_g  = (const float*)d_in[8];
    const float* ln2_b  = (const float*)d_in[9];
    const float* W1     = (const float*)d_in[10];
    const float* b1     = (const float*)d_in[11];
    const float* W2     = (const float*)d_in[12];
    const float* b2     = (const float*)d_in[13];
    const float* Wout   = (const float*)d_in[14];
    const float* bout   = (const float*)d_in[15];
    float* out = (float*)d_out;

    float *y, *h, *htf, *q, *k, *v, *s, *ao, *u, *wq, *wk, *wv, *w1, *w2;
    cudaGetSymbolAddress((void**)&y,   g_y);
    cudaGetSymbolAddress((void**)&h,   g_h);
    cudaGetSymbolAddress((void**)&htf, g_htf);
    cudaGetSymbolAddress((void**)&q,   g_q);
    cudaGetSymbolAddress((void**)&k,   g_k);
    cudaGetSymbolAddress((void**)&v,   g_v);
    cudaGetSymbolAddress((void**)&s,   g_s);
    cudaGetSymbolAddress((void**)&ao,  g_ao);
    cudaGetSymbolAddress((void**)&u,   g_u);
    cudaGetSymbolAddress((void**)&wq,  g_wq);
    cudaGetSymbolAddress((void**)&wk,  g_wk);
    cudaGetSymbolAddress((void**)&wv,  g_wv);
    cudaGetSymbolAddress((void**)&w1,  g_w1);
    cudaGetSymbolAddress((void**)&w2,  g_w2);

    const int MBT = Bb * Tt;  // 8192
    const long long WqkvStride = (long long)Hh * Dd * Ee;
    const int NQKV = Ll * Hh * Dd * Ee;   // 10.49M
    const int NMLP = Ll * 4 * Ee * Ee;    // 5.24M

    // pre-convert all weights to tf32
    cvtw_kernel<<<NQKV / 1024, 256>>>(Wq, wq);
    cvtw_kernel<<<NQKV / 1024, 256>>>(Wk, wk);
    cvtw_kernel<<<NQKV / 1024, 256>>>(Wv, wv);
    cvtw_kernel<<<NMLP / 1024, 256>>>(W1, w1);
    cvtw_kernel<<<NMLP / 1024, 256>>>(W2, w2);

    embed_kernel<<<(MBT * Ee) / 256, 256>>>(tokens, emb, pos, y);

    for (int l = 0; l < Ll; l++) {
        ln_kernel<<<MBT, 256>>>(y, ln1_g + l * Ee, ln1_b + l * Ee, h, htf);

        dim3 gqkv(4096 / BN, MBT / BM);
        gemm_tc<true, EPI_QKV, false><<<gqkv, 256>>>(htf, wq + l * WqkvStride, q,
            MBT, Hh * Dd, Ee, 0, 0, 0, nullptr, nullptr);
        gemm_tc<true, EPI_QKV, false><<<gqkv, 256>>>(htf, wk + l * WqkvStride, k,
            MBT, Hh * Dd, Ee, 0, 0, 0, nullptr, nullptr);
        gemm_tc<true, EPI_QKV, false><<<gqkv, 256>>>(htf, wv + l * WqkvStride, v,
            MBT, Hh * Dd, Ee, 0, 0, 0, nullptr, nullptr);

        dim3 gqk(Tt / BN, Tt / BM, Bb * Hh);
        gemm_tc<true, EPI_CAUSAL, false><<<gqk, 256>>>(q, k, s,
            Tt, Tt, Dd, (long long)TD, (long long)TD, (long long)TT, nullptr, nullptr);

        softmax_kernel<<<Bb * Hh * Tt, 256>>>(s);

        dim3 gav(Dd / BN, Tt / BM, Bb * Hh);
        gemm_tc<false, EPI_PLAIN, true><<<gav, 256>>>(s, v, ao,
            Tt, Dd, Tt, (long long)TT, (long long)TD, (long long)TD, nullptr, nullptr);

        headsum_kernel<<<(MBT * Ee) / 1024, 256>>>(ao, y);

        ln_kernel<<<MBT, 256>>>(y, ln2_g + l * Ee, ln2_b + l * Ee, h, htf);

        dim3 g1((4 * Ee) / BN, MBT / BM);
        gemm_tc<true, EPI_BIASRELU, false><<<g1, 256>>>(htf, w1 + (long long)l * 4 * Ee * Ee, u,
            MBT, 4 * Ee, Ee, 0, 0, 0, b1 + l * 4 * Ee, nullptr);

        dim3 g2(Ee / BN, MBT / BM);
        gemm_tc<true, EPI_BIASRES, false><<<g2, 256>>>(u, w2 + (long long)l * Ee * 4 * Ee, y,
            MBT, Ee, 4 * Ee, 0, 0, 0, b2 + l * Ee, h);
    }

    logits_kernel<<<MBT / 8, 256>>>(y, Wout, bout, out);
}

// round 6
// speedup vs baseline: 3.2330x; 1.0850x over previous
#include <cuda_runtime.h>
#include <cuda_bf16.h>
#include <cstdint>

// ---------------- problem constants ----------------
#define Bb 4
#define Tt 2048
#define Ee 512
#define Hh 8
#define Ll 5
#define Vv 130
#define Dd 512
#define TD (Tt * Dd)
#define TT (Tt * Tt)

// ---------------- device scratch ----------------
__device__ float g_y[Bb * Tt * Ee];                  // residual stream (fp32)
__device__ float g_h[Bb * Tt * Ee];                  // LN output fp32 (residual source)
__device__ float g_htf[Bb * Tt * Ee];                // LN output tf32 (GEMM A operand)
__device__ float g_q[Bb * Hh * Tt * Dd];             // tf32
__device__ float g_k[Bb * Hh * Tt * Dd];             // tf32
__device__ float g_v[Bb * Hh * Tt * Dd];             // tf32
__device__ float g_s[(long long)Bb * Hh * Tt * Tt];  // scores; tf32 after softmax
__device__ float g_ao[Bb * Hh * Tt * Dd];            // fp32 per-head attn out
__device__ float g_u[Bb * Tt * 4 * Ee];              // MLP hidden, tf32
// pre-converted tf32 weights
__device__ float g_wq[Ll * Hh * Dd * Ee];
__device__ float g_wk[Ll * Hh * Dd * Ee];
__device__ float g_wv[Ll * Hh * Dd * Ee];
__device__ float g_w1[Ll * 4 * Ee * Ee];
__device__ float g_w2[Ll * 4 * Ee * Ee];

// ---------------- tf32 helpers ----------------
__device__ __forceinline__ uint32_t f2tf32(float x) {
    uint32_t u;
    asm("cvt.rna.tf32.f32 %0, %1;" : "=r"(u) : "f"(x));
    return u;
}
__device__ __forceinline__ float f2tf32f(float x) { return __uint_as_float(f2tf32(x)); }
__device__ __forceinline__ void cpa16(uint32_t s, const void* g) {
    asm volatile("cp.async.cg.shared.global [%0], [%1], 16;" :: "r"(s), "l"(g));
}

// ---------------- weight pre-conversion (fp32 -> tf32 bits) ----------------
__global__ void cvtw_kernel(const float* __restrict__ src, float* __restrict__ dst)
{
    const long long i = ((long long)blockIdx.x * 256 + threadIdx.x) << 2;
    float4 v = *reinterpret_cast<const float4*>(&src[i]);
    v.x = f2tf32f(v.x); v.y = f2tf32f(v.y); v.z = f2tf32f(v.z); v.w = f2tf32f(v.w);
    *reinterpret_cast<float4*>(&dst[i]) = v;
}

// ---------------- tf32 tensor-core GEMM, 3-stage cp.async + frag double-buffer ----------------
constexpr int BM = 128, BN = 128, BK = 16;
constexpr int APAD = 20;
constexpr int BPAD_NN = 136;
constexpr int STAGES = 3;
constexpr int A_STAGE = BM * APAD;                    // floats per A stage
constexpr int B_STAGE_NT = BN * APAD;
constexpr int B_STAGE_NN = BK * BPAD_NN;
constexpr int SMEM_NT_BYTES = STAGES * (A_STAGE + B_STAGE_NT) * 4;  // 61440
constexpr int SMEM_NN_BYTES = STAGES * (A_STAGE + B_STAGE_NN) * 4;  // 56832

enum { EPI_PLAIN = 0, EPI_QKV = 1, EPI_CAUSAL = 2, EPI_BIASRELU = 3, EPI_BIASRES = 4 };

template <int EPI>
__device__ __forceinline__ void store_pair(float* __restrict__ C, const float* __restrict__ bias,
                                           const float* __restrict__ Res, int N,
                                           int m, int n, float v0, float v1)
{
    if (EPI == EPI_PLAIN) {
        *reinterpret_cast<float2*>(&C[(long long)m * N + n]) = make_float2(v0, v1);
    } else if (EPI == EPI_QKV) {
        const int b_ = m >> 11, t = m & (Tt - 1);
        const int h = n >> 9, d = n & (Dd - 1);
        *reinterpret_cast<float2*>(&C[((long long)(b_ * Hh + h) << 20) + ((long long)t << 9) + d]) =
            make_float2(f2tf32f(v0), f2tf32f(v1));
    } else if (EPI == EPI_CAUSAL) {
        v0 *= 0.044194173824159216f;
        v1 *= 0.044194173824159216f;
        if (n > m)     v0 = -1e30f;
        if (n + 1 > m) v1 = -1e30f;
        *reinterpret_cast<float2*>(&C[(long long)m * N + n]) = make_float2(v0, v1);
    } else if (EPI == EPI_BIASRELU) {
        v0 = f2tf32f(fmaxf(v0 + bias[n], 0.f));
        v1 = f2tf32f(fmaxf(v1 + bias[n + 1], 0.f));
        *reinterpret_cast<float2*>(&C[(long long)m * N + n]) = make_float2(v0, v1);
    } else {  // EPI_BIASRES: full fp32 residual
        const float2 r = *reinterpret_cast<const float2*>(&Res[(long long)m * N + n]);
        v0 += bias[n] + r.x;
        v1 += bias[n + 1] + r.y;
        *reinterpret_cast<float2*>(&C[(long long)m * N + n]) = make_float2(v0, v1);
    }
}

// C = A * op(B); A row-major [M,K]; BNT: B row-major [N,K] (NT) else [K,N] (NN)
// All A/B inputs are ALREADY tf32-rounded fp32 bit patterns.
template <bool BNT, int EPI, bool CK>
__global__ __launch_bounds__(256, 2) void gemm_tc(
    const float* __restrict__ A, const float* __restrict__ B, float* __restrict__ C,
    int M, int N, int K,
    long long sA_, long long sB_, long long sC_,
    const float* __restrict__ bias, const float* __restrict__ Res)
{
    const int bx = blockIdx.x, by = blockIdx.y, bz = blockIdx.z;
    if (EPI == EPI_CAUSAL && bx > by) return;

    A += (long long)bz * sA_;
    B += (long long)bz * sB_;
    C += (long long)bz * sC_;

    int Keff = K;
    if (CK) { int ke = (by + 1) * BM; Keff = ke < K ? ke : K; }
    const int NT = Keff / BK;

    constexpr int B_STAGE = BNT ? B_STAGE_NT : B_STAGE_NN;
    constexpr int STAGE_SZ = A_STAGE + B_STAGE;
    extern __shared__ float smem[];

    const int tid = threadIdx.x;
    const int wid = tid >> 5, lane = tid & 31;
    const int g = lane >> 2, tig = lane & 3;
    const int wm = wid & 1, wn = wid >> 1;     // 2x4 warp grid; warp tile 64x32
    const int m0 = by * BM, n0 = bx * BN;

    const int ar = tid >> 2, ac = (tid & 3) << 2;
    const int br = tid >> 5, bc = (tid & 31) << 2;

    float c[4][4][4];
#pragma unroll
    for (int i = 0; i < 4; i++)
#pragma unroll
        for (int j = 0; j < 4; j++)
#pragma unroll
            for (int q = 0; q < 4; q++) c[i][j][q] = 0.f;

    auto loadTiles = [&](int st, int kt) {
        const int k0 = kt * BK;
        float* sA = smem + st * STAGE_SZ;
        float* sB = sA + A_STAGE;
#pragma unroll
        for (int r = 0; r < BM; r += 64) {
            uint32_t d = (uint32_t)__cvta_generic_to_shared(&sA[(ar + r) * APAD + ac]);
            cpa16(d, &A[(long long)(m0 + ar + r) * K + k0 + ac]);
        }
        if (BNT) {
#pragma unroll
            for (int r = 0; r < BN; r += 64) {
                uint32_t d = (uint32_t)__cvta_generic_to_shared(&sB[(ar + r) * APAD + ac]);
                cpa16(d, &B[(long long)(n0 + ar + r) * K + k0 + ac]);
            }
        } else {
#pragma unroll
            for (int r = 0; r < BK; r += 8) {
                uint32_t d = (uint32_t)__cvta_generic_to_shared(&sB[(br + r) * BPAD_NN + bc]);
                cpa16(d, &B[(long long)(k0 + br + r) * N + n0 + bc]);
            }
        }
    };

    auto loadFragA = [&](uint32_t af[4][4], int st, int k0) {
        const float* sA = smem + st * STAGE_SZ;
#pragma unroll
        for (int mt = 0; mt < 4; mt++) {
            const uint32_t* base = reinterpret_cast<const uint32_t*>(
                &sA[(wm * 64 + mt * 16 + g) * APAD + k0 + tig]);
            af[mt][0] = base[0];
            af[mt][1] = base[8 * APAD];
            af[mt][2] = base[4];
            af[mt][3] = base[8 * APAD + 4];
        }
    };
    auto loadFragB = [&](uint32_t bf[4][2], int st, int k0) {
        const float* sB = smem + st * STAGE_SZ + A_STAGE;
#pragma unroll
        for (int nt = 0; nt < 4; nt++) {
            if (BNT) {
                const uint32_t* base = reinterpret_cast<const uint32_t*>(
                    &sB[(wn * 32 + nt * 8 + g) * APAD + k0 + tig]);
                bf[nt][0] = base[0];
                bf[nt][1] = base[4];
            } else {
                const uint32_t* base = reinterpret_cast<const uint32_t*>(
                    &sB[(k0 + tig) * BPAD_NN + wn * 32 + nt * 8 + g]);
                bf[nt][0] = base[0];
                bf[nt][1] = base[4 * BPAD_NN];
            }
        }
    };
    auto mma16 = [&](const uint32_t af[4][4], const uint32_t bf[4][2]) {
#pragma unroll
        for (int mt = 0; mt < 4; mt++)
#pragma unroll
            for (int nt = 0; nt < 4; nt++) {
                asm volatile(
                    "mma.sync.aligned.m16n8k8.row.col.f32.tf32.tf32.f32 "
                    "{%0,%1,%2,%3}, {%4,%5,%6,%7}, {%8,%9}, {%0,%1,%2,%3};"
                    : "+f"(c[mt][nt][0]), "+f"(c[mt][nt][1]),
                      "+f"(c[mt][nt][2]), "+f"(c[mt][nt][3])
                    : "r"(af[mt][0]), "r"(af[mt][1]), "r"(af[mt][2]), "r"(af[mt][3]),
                      "r"(bf[nt][0]), "r"(bf[nt][1]));
            }
    };

    // ---- prologue: fill 2 stages, preload tile-0 k0=0 fragments ----
    loadTiles(0, 0);
    asm volatile("cp.async.commit_group;");
    if (NT > 1) {
        loadTiles(1, 1);
        asm volatile("cp.async.commit_group;");
        asm volatile("cp.async.wait_group 1;");
    } else {
        asm volatile("cp.async.wait_group 0;");
    }
    __syncthreads();

    uint32_t afA[4][4], bfA[4][2], afB[4][4], bfB[4][2];
    loadFragA(afA, 0, 0);
    loadFragB(bfA, 0, 0);

    // ---- main loop: per tile, frag-double-buffered halves ----
    for (int it = 0; it < NT; ++it) {
        const int st = it % 3;
        loadFragA(afB, st, 8);                      // second half of current tile
        loadFragB(bfB, st, 8);
        if (it + 2 < NT) {                          // keep pipeline 2 tiles deep
            loadTiles((it + 2) % 3, it + 2);
            asm volatile("cp.async.commit_group;");
        }
        mma16(afA, bfA);
        if (it + 1 < NT) {
            if (it + 2 < NT) asm volatile("cp.async.wait_group 1;");
            else             asm volatile("cp.async.wait_group 0;");
            __syncthreads();
            loadFragA(afA, (it + 1) % 3, 0);        // first half of next tile
            loadFragB(bfA, (it + 1) % 3, 0);
        }
        mma16(afB, bfB);
    }

    // ---- epilogue ----
#pragma unroll
    for (int mt = 0; mt < 4; mt++) {
        const int mrow = m0 + wm * 64 + mt * 16 + g;
#pragma unroll
        for (int nt = 0; nt < 4; nt++) {
            const int ncol = n0 + wn * 32 + nt * 8 + tig * 2;
            store_pair<EPI>(C, bias, Res, N, mrow,     ncol, c[mt][nt][0], c[mt][nt][1]);
            store_pair<EPI>(C, bias, Res, N, mrow + 8, ncol, c[mt][nt][2], c[mt][nt][3]);
        }
    }
}

// ---------------- LayerNorm: writes fp32 copy (residual) + tf32 copy (GEMM A) ----------------
__global__ void ln_kernel(const float* __restrict__ x, const float* __restrict__ g,
                          const float* __restrict__ b, float* __restrict__ out,
                          float* __restrict__ out_tf)
{
    const int row = blockIdx.x;
    const float* xr = x + (long long)row * Ee;
    const int tid = threadIdx.x;  // 256
    float v0 = xr[tid], v1 = xr[tid + 256];
    float s = v0 + v1, sq = v0 * v0 + v1 * v1;
#pragma unroll
    for (int o = 16; o; o >>= 1) {
        s  += __shfl_xor_sync(0xffffffffu, s,  o);
        sq += __shfl_xor_sync(0xffffffffu, sq, o);
    }
    __shared__ float ss[8], sqq[8];
    const int warp = tid >> 5, lane = tid & 31;
    if (lane == 0) { ss[warp] = s; sqq[warp] = sq; }
    __syncthreads();
    if (tid == 0) {
        float a = 0.f, c2 = 0.f;
#pragma unroll
        for (int i = 0; i < 8; i++) { a += ss[i]; c2 += sqq[i]; }
        ss[0] = a; sqq[0] = c2;
    }
    __syncthreads();
    const float mu  = ss[0] * (1.f / 512.f);
    const float var = sqq[0] * (1.f / 512.f) - mu * mu;
    const float r = rsqrtf(var + 1e-5f);
    const float o0 = (v0 - mu) * r * g[tid]       + b[tid];
    const float o1 = (v1 - mu) * r * g[tid + 256] + b[tid + 256];
    out[(long long)row * Ee + tid]          = o0;
    out[(long long)row * Ee + tid + 256]    = o1;
    out_tf[(long long)row * Ee + tid]       = f2tf32f(o0);
    out_tf[(long long)row * Ee + tid + 256] = f2tf32f(o1);
}

// ---------------- causal softmax: stores tf32-rounded probabilities ----------------
__global__ void softmax_kernel(float* __restrict__ S)
{
    const long long r = blockIdx.x;
    const int t = (int)(r & (Tt - 1));
    float* row = S + (r << 11);
    const int len4 = (((t >> 7) + 1) << 7) >> 2;
    const int tid = threadIdx.x;  // 256

    float4 e[2];
    float mx = -1e30f;
#pragma unroll
    for (int c = 0; c < 2; c++) {
        const int i = tid + c * 256;
        if (i < len4) {
            e[c] = *reinterpret_cast<const float4*>(&row[i << 2]);
            mx = fmaxf(fmaxf(fmaxf(e[c].x, e[c].y), fmaxf(e[c].z, e[c].w)), mx);
        }
    }
    __shared__ float redmax[8], redsum[8];
#pragma unroll
    for (int o = 16; o; o >>= 1) mx = fmaxf(mx, __shfl_xor_sync(0xffffffffu, mx, o));
    const int warp = tid >> 5, lane = tid & 31;
    if (lane == 0) redmax[warp] = mx;
    __syncthreads();
    mx = redmax[0];
#pragma unroll
    for (int w = 1; w < 8; w++) mx = fmaxf(mx, redmax[w]);

    float sum = 0.f;
#pragma unroll
    for (int c = 0; c < 2; c++) {
        const int i = tid + c * 256;
        if (i < len4) {
            e[c].x = expf(e[c].x - mx); e[c].y = expf(e[c].y - mx);
            e[c].z = expf(e[c].z - mx); e[c].w = expf(e[c].w - mx);
            sum += (e[c].x + e[c].y) + (e[c].z + e[c].w);
        }
    }
#pragma unroll
    for (int o = 16; o; o >>= 1) sum += __shfl_xor_sync(0xffffffffu, sum, o);
    if (lane == 0) redsum[warp] = sum;
    __syncthreads();
    sum = 0.f;
#pragma unroll
    for (int w = 0; w < 8; w++) sum += redsum[w];
    const float inv = 1.f / sum;
#pragma unroll
    for (int c = 0; c < 2; c++) {
        const int i = tid + c * 256;
        if (i < len4) {
            e[c].x = f2tf32f(e[c].x * inv); e[c].y = f2tf32f(e[c].y * inv);
            e[c].z = f2tf32f(e[c].z * inv); e[c].w = f2tf32f(e[c].w * inv);
            *reinterpret_cast<float4*>(&row[i << 2]) = e[c];
        }
    }
}

// ---------------- embedding ----------------
__global__ void embed_kernel(const int* __restrict__ tokens, const float* __restrict__ emb,
                             const float* __restrict__ pos, float* __restrict__ y)
{
    const long long idx = (long long)blockIdx.x * 256 + threadIdx.x;
    const int e = (int)(idx & (Ee - 1));
    const long long m = idx >> 9;
    const int t = (int)(m & (Tt - 1));
    const int tok = tokens[m];
    y[idx] = emb[(long long)tok * Ee + e] + pos[(long long)t * Ee + e];
}

// ---------------- head sum + residual (float4) ----------------
__global__ void headsum_kernel(const float* __restrict__ ao, float* __restrict__ y)
{
    const long long i4 = (long long)blockIdx.x * 256 + threadIdx.x;
    const long long idx = i4 << 2;
    const int e = (int)(idx & (Ee - 1));
    const long long m = idx >> 9;
    const int b_ = (int)(m >> 11);
    const int t = (int)(m & (Tt - 1));
    float4 s = *reinterpret_cast<const float4*>(&y[idx]);
    const long long base = ((long long)(b_ * Hh) << 20) + ((long long)t << 9) + e;
#pragma unroll
    for (int h = 0; h < Hh; h++) {
        float4 a = *reinterpret_cast<const float4*>(&ao[base + ((long long)h << 20)]);
        s.x += a.x; s.y += a.y; s.z += a.z; s.w += a.w;
    }
    *reinterpret_cast<float4*>(&y[idx]) = s;
}

// ---------------- logits: warp per row, N=130 ----------------
__global__ void logits_kernel(const float* __restrict__ y, const float* __restrict__ Wout,
                              const float* __restrict__ bout, float* __restrict__ out)
{
    const int warp = threadIdx.x >> 5, lane = threadIdx.x & 31;
    const int m = blockIdx.x * 8 + warp;
    const float* yr = y + (long long)m * Ee;
    float yreg[16];
#pragma unroll
    for (int i = 0; i < 16; i++) yreg[i] = yr[lane + i * 32];
    for (int n = 0; n < Vv; n++) {
        const float* w = Wout + (long long)n * Ee;
        float s = 0.f;
#pragma unroll
        for (int i = 0; i < 16; i++) s = fmaf(yreg[i], w[lane + i * 32], s);
#pragma unroll
        for (int o = 16; o; o >>= 1) s += __shfl_xor_sync(0xffffffffu, s, o);
        if (lane == 0) out[(long long)m * Vv + n] = s + bout[n];
    }
}

// ---------------- driver ----------------
extern "C" void kernel_launch(void* const* d_in, const int* in_sizes, int n_in,
                              void* d_out, int out_size)
{
    const int*   tokens = (const int*)  d_in[0];
    const float* emb    = (const float*)d_in[1];
    const float* pos    = (const float*)d_in[2];
    const float* ln1_g  = (const float*)d_in[3];
    const float* ln1_b  = (const float*)d_in[4];
    const float* Wq     = (const float*)d_in[5];
    const float* Wk     = (const float*)d_in[6];
    const float* Wv     = (const float*)d_in[7];
    const float* ln2_g  = (const float*)d_in[8];
    const float* ln2_b  = (const float*)d_in[9];
    const float* W1     = (const float*)d_in[10];
    const float* b1     = (const float*)d_in[11];
    const float* W2     = (const float*)d_in[12];
    const float* b2     = (const float*)d_in[13];
    const float* Wout   = (const float*)d_in[14];
    const float* bout   = (const float*)d_in[15];
    float* out = (float*)d_out;

    float *y, *h, *htf, *q, *k, *v, *s, *ao, *u, *wq, *wk, *wv, *w1, *w2;
    cudaGetSymbolAddress((void**)&y,   g_y);
    cudaGetSymbolAddress((void**)&h,   g_h);
    cudaGetSymbolAddress((void**)&htf, g_htf);
    cudaGetSymbolAddress((void**)&q,   g_q);
    cudaGetSymbolAddress((void**)&k,   g_k);
    cudaGetSymbolAddress((void**)&v,   g_v);
    cudaGetSymbolAddress((void**)&s,   g_s);
    cudaGetSymbolAddress((void**)&ao,  g_ao);
    cudaGetSymbolAddress((void**)&u,   g_u);
    cudaGetSymbolAddress((void**)&wq,  g_wq);
    cudaGetSymbolAddress((void**)&wk,  g_wk);
    cudaGetSymbolAddress((void**)&wv,  g_wv);
    cudaGetSymbolAddress((void**)&w1,  g_w1);
    cudaGetSymbolAddress((void**)&w2,  g_w2);

    // raise dynamic smem limit for the 3-stage pipeline (idempotent, deterministic)
    cudaFuncSetAttribute(gemm_tc<true,  EPI_QKV,     false>, cudaFuncAttributeMaxDynamicSharedMemorySize, SMEM_NT_BYTES);
    cudaFuncSetAttribute(gemm_tc<true,  EPI_CAUSAL,  false>, cudaFuncAttributeMaxDynamicSharedMemorySize, SMEM_NT_BYTES);
    cudaFuncSetAttribute(gemm_tc<false, EPI_PLAIN,   true >, cudaFuncAttributeMaxDynamicSharedMemorySize, SMEM_NN_BYTES);
    cudaFuncSetAttribute(gemm_tc<true,  EPI_BIASRELU,false>, cudaFuncAttributeMaxDynamicSharedMemorySize, SMEM_NT_BYTES);
    cudaFuncSetAttribute(gemm_tc<true,  EPI_BIASRES, false>, cudaFuncAttributeMaxDynamicSharedMemorySize, SMEM_NT_BYTES);

    const int MBT = Bb * Tt;  // 8192
    const long long WqkvStride = (long long)Hh * Dd * Ee;
    const int NQKV = Ll * Hh * Dd * Ee;   // 10.49M
    const int NMLP = Ll * 4 * Ee * Ee;    // 5.24M

    // pre-convert all weights to tf32
    cvtw_kernel<<<NQKV / 1024, 256>>>(Wq, wq);
    cvtw_kernel<<<NQKV / 1024, 256>>>(Wk, wk);
    cvtw_kernel<<<NQKV / 1024, 256>>>(Wv, wv);
    cvtw_kernel<<<NMLP / 1024, 256>>>(W1, w1);
    cvtw_kernel<<<NMLP / 1024, 256>>>(W2, w2);

    embed_kernel<<<(MBT * Ee) / 256, 256>>>(tokens, emb, pos, y);

    for (int l = 0; l < Ll; l++) {
        ln_kernel<<<MBT, 256>>>(y, ln1_g + l * Ee, ln1_b + l * Ee, h, htf);

        dim3 gqkv(4096 / BN, MBT / BM);
        gemm_tc<true, EPI_QKV, false><<<gqkv, 256, SMEM_NT_BYTES>>>(htf, wq + l * WqkvStride, q,
            MBT, Hh * Dd, Ee, 0, 0, 0, nullptr, nullptr);
        gemm_tc<true, EPI_QKV, false><<<gqkv, 256, SMEM_NT_BYTES>>>(htf, wk + l * WqkvStride, k,
            MBT, Hh * Dd, Ee, 0, 0, 0, nullptr, nullptr);
        gemm_tc<true, EPI_QKV, false><<<gqkv, 256, SMEM_NT_BYTES>>>(htf, wv + l * WqkvStride, v,
            MBT, Hh * Dd, Ee, 0, 0, 0, nullptr, nullptr);

        dim3 gqk(Tt / BN, Tt / BM, Bb * Hh);
        gemm_tc<true, EPI_CAUSAL, false><<<gqk, 256, SMEM_NT_BYTES>>>(q, k, s,
            Tt, Tt, Dd, (long long)TD, (long long)TD, (long long)TT, nullptr, nullptr);

        softmax_kernel<<<Bb * Hh * Tt, 256>>>(s);

        dim3 gav(Dd / BN, Tt / BM, Bb * Hh);
        gemm_tc<false, EPI_PLAIN, true><<<gav, 256, SMEM_NN_BYTES>>>(s, v, ao,
            Tt, Dd, Tt, (long long)TT, (long long)TD, (long long)TD, nullptr, nullptr);

        headsum_kernel<<<(MBT * Ee) / 1024, 256>>>(ao, y);

        ln_kernel<<<MBT, 256>>>(y, ln2_g + l * Ee, ln2_b + l * Ee, h, htf);

        dim3 g1((4 * Ee) / BN, MBT / BM);
        gemm_tc<true, EPI_BIASRELU, false><<<g1, 256, SMEM_NT_BYTES>>>(htf, w1 + (long long)l * 4 * Ee * Ee, u,
            MBT, 4 * Ee, Ee, 0, 0, 0, b1 + l * 4 * Ee, nullptr);

        dim3 g2(Ee / BN, MBT / BM);
        gemm_tc<true, EPI_BIASRES, false><<<g2, 256, SMEM_NT_BYTES>>>(u, w2 + (long long)l * Ee * 4 * Ee, y,
            MBT, Ee, 4 * Ee, 0, 0, 0, b2 + l * Ee, h);
    }

    logits_kernel<<<MBT / 8, 256>>>(y, Wout, bout, out);
}

// round 10
// speedup vs baseline: 5.5363x; 1.7124x over previous
#include <cuda_runtime.h>
#include <cuda_fp16.h>
#include <cstdint>

// ---------------- problem constants ----------------
#define Bb 4
#define Tt 2048
#define Ee 512
#define Hh 8
#define Ll 5
#define Vv 130
#define Dd 512
#define TD (Tt * Dd)
#define TT (Tt * Tt)

// ---------------- device scratch ----------------
__device__ float  g_y[Bb * Tt * Ee];                  // residual stream fp32
__device__ float  g_h[Bb * Tt * Ee];                  // LN output fp32 (residual source)
__device__ __half g_hh[Bb * Tt * Ee];                 // LN output fp16 (GEMM A)
__device__ __half g_qh[Bb * Tt * Hh * Dd];            // Q plain [B*T, H*D]
__device__ __half g_kh[Bb * Tt * Hh * Dd];            // K plain
__device__ __half g_vh[Bb * Tt * Hh * Dd];            // V plain
__device__ __half g_vt[Bb * Hh * Dd * Tt];            // V transposed [B,H,D,T]
__device__ float  g_s[(long long)Bb * Hh * Tt * Tt];  // scores fp32
__device__ __half g_sh[(long long)Bb * Hh * Tt * Tt]; // softmax probs fp16
__device__ float  g_ao[Bb * Hh * Tt * Dd];            // per-head attn out fp32
__device__ __half g_uh[Bb * Tt * 4 * Ee];             // MLP hidden fp16
__device__ __half g_wq[Ll * Hh * Dd * Ee];
__device__ __half g_wk[Ll * Hh * Dd * Ee];
__device__ __half g_wv[Ll * Hh * Dd * Ee];
__device__ __half g_w1[Ll * 4 * Ee * Ee];
__device__ __half g_w2[Ll * 4 * Ee * Ee];

// ---------------- helpers ----------------
__device__ __forceinline__ void cpa16(uint32_t s, const void* g) {
    asm volatile("cp.async.cg.shared.global [%0], [%1], 16;" :: "r"(s), "l"(g));
}

// ---------------- weight pre-conversion (fp32 -> fp16) ----------------
__global__ void cvtwh_kernel(const float* __restrict__ src, __half* __restrict__ dst)
{
    const long long i = ((long long)blockIdx.x * 256 + threadIdx.x) << 2;
    float4 v = *reinterpret_cast<const float4*>(&src[i]);
    __half2 a = __floats2half2_rn(v.x, v.y);
    __half2 b = __floats2half2_rn(v.z, v.w);
    uint2 pk;
    pk.x = *reinterpret_cast<uint32_t*>(&a);
    pk.y = *reinterpret_cast<uint32_t*>(&b);
    *reinterpret_cast<uint2*>(&dst[i]) = pk;
}

// ---------------- fp16 tensor-core GEMM (m16n8k16), 3-stage cp.async + frag dbuf ----------------
// C = A * B^T ; A row-major [M,K] lda halfs; B row-major [N,K] ldb halfs (NT). 256 thr.
constexpr int BKH = 32;                 // halfs per k-tile (64 bytes)
constexpr int ROWB = 80;                // smem bytes per row (64 + 16 pad; conflict-free)
constexpr int A_STAGE_B = 128 * ROWB;   // 10240 B
constexpr int STAGE_B = 2 * A_STAGE_B;  // 20480 B
constexpr int GSMEM_B = 3 * STAGE_B;    // 61440 B

enum { EPI_F32 = 0, EPI_H = 1, EPI_CAUSAL = 2, EPI_HRELU = 3, EPI_BIASRES = 4 };

template <int EPI>
__device__ __forceinline__ void storep(float* __restrict__ Cf, __half* __restrict__ Ch,
                                       const float* __restrict__ bias, const float* __restrict__ Res,
                                       int ldc, int m, int n, float v0, float v1)
{
    if (EPI == EPI_F32) {
        *reinterpret_cast<float2*>(&Cf[(long long)m * ldc + n]) = make_float2(v0, v1);
    } else if (EPI == EPI_H) {
        *reinterpret_cast<__half2*>(&Ch[(long long)m * ldc + n]) = __floats2half2_rn(v0, v1);
    } else if (EPI == EPI_CAUSAL) {
        v0 *= 0.044194173824159216f;
        v1 *= 0.044194173824159216f;
        if (n > m)     v0 = -1e30f;
        if (n + 1 > m) v1 = -1e30f;
        *reinterpret_cast<float2*>(&Cf[(long long)m * ldc + n]) = make_float2(v0, v1);
    } else if (EPI == EPI_HRELU) {
        v0 = fmaxf(v0 + bias[n], 0.f);
        v1 = fmaxf(v1 + bias[n + 1], 0.f);
        *reinterpret_cast<__half2*>(&Ch[(long long)m * ldc + n]) = __floats2half2_rn(v0, v1);
    } else {  // EPI_BIASRES
        const float2 r = *reinterpret_cast<const float2*>(&Res[(long long)m * ldc + n]);
        *reinterpret_cast<float2*>(&Cf[(long long)m * ldc + n]) =
            make_float2(v0 + bias[n] + r.x, v1 + bias[n + 1] + r.y);
    }
}

template <int EPI, bool CK, bool ZQK>
__global__ __launch_bounds__(256, 2) void gemmh(
    const __half* __restrict__ A, const __half* __restrict__ B, void* __restrict__ Cv,
    int lda, int ldb, int ldc, int K,
    long long sA_, long long sB_, long long sC_,
    const float* __restrict__ bias, const float* __restrict__ Res)
{
    const int bx = blockIdx.x, by = blockIdx.y, bz = blockIdx.z;
    if (EPI == EPI_CAUSAL && bx > by) return;  // causal: skip strictly-upper tiles

    long long offA, offB;
    if (ZQK) {
        const int b_ = bz >> 3, h_ = bz & 7;
        offA = offB = (long long)b_ * Tt * 4096 + h_ * 512;
    } else {
        offA = (long long)bz * sA_;
        offB = (long long)bz * sB_;
    }
    A += offA; B += offB;
    float*  Cf = (float*)Cv + (long long)bz * sC_;
    __half* Ch = (__half*)Cv + (long long)bz * sC_;

    int Keff = K;
    if (CK) { int ke = (by + 1) * 128; Keff = ke < K ? ke : K; }
    const int NT = Keff / BKH;

    extern __shared__ char smem[];

    const int tid = threadIdx.x;
    const int wid = tid >> 5, lane = tid & 31;
    const int g = lane >> 2, tig = lane & 3;
    const int wm = wid & 1, wn = wid >> 1;     // 2x4 warp grid; warp tile 64x32
    const int m0 = by * 128, n0 = bx * 128;
    const int lr = tid >> 2, lc = tid & 3;     // loader: row 0..63(+64), 16B chunk 0..3

    float c[4][4][4];
#pragma unroll
    for (int i = 0; i < 4; i++)
#pragma unroll
        for (int j = 0; j < 4; j++)
#pragma unroll
            for (int q = 0; q < 4; q++) c[i][j][q] = 0.f;

    auto loadTiles = [&](int st, int kt) {
        const int k0 = kt * BKH;
        char* sA = smem + st * STAGE_B;
        char* sB = sA + A_STAGE_B;
#pragma unroll
        for (int r0 = 0; r0 < 128; r0 += 64) {
            const int r = lr + r0;
            cpa16((uint32_t)__cvta_generic_to_shared(sA + r * ROWB + lc * 16),
                  A + (long long)(m0 + r) * lda + k0 + lc * 8);
            cpa16((uint32_t)__cvta_generic_to_shared(sB + r * ROWB + lc * 16),
                  B + (long long)(n0 + r) * ldb + k0 + lc * 8);
        }
    };

    auto loadFragA = [&](uint32_t af[4][4], int st, int kb) {
        const char* sA = smem + st * STAGE_B;
#pragma unroll
        for (int mt = 0; mt < 4; mt++) {
            const char* base = sA + (wm * 64 + mt * 16 + g) * ROWB + kb + tig * 4;
            af[mt][0] = *reinterpret_cast<const uint32_t*>(base);
            af[mt][1] = *reinterpret_cast<const uint32_t*>(base + 8 * ROWB);
            af[mt][2] = *reinterpret_cast<const uint32_t*>(base + 16);
            af[mt][3] = *reinterpret_cast<const uint32_t*>(base + 8 * ROWB + 16);
        }
    };
    auto loadFragB = [&](uint32_t bf[4][2], int st, int kb) {
        const char* sB = smem + st * STAGE_B + A_STAGE_B;
#pragma unroll
        for (int nt = 0; nt < 4; nt++) {
            const char* base = sB + (wn * 32 + nt * 8 + g) * ROWB + kb + tig * 4;
            bf[nt][0] = *reinterpret_cast<const uint32_t*>(base);
            bf[nt][1] = *reinterpret_cast<const uint32_t*>(base + 16);
        }
    };
    auto mma16 = [&](const uint32_t af[4][4], const uint32_t bf[4][2]) {
#pragma unroll
        for (int mt = 0; mt < 4; mt++)
#pragma unroll
            for (int nt = 0; nt < 4; nt++) {
                asm volatile(
                    "mma.sync.aligned.m16n8k16.row.col.f32.f16.f16.f32 "
                    "{%0,%1,%2,%3}, {%4,%5,%6,%7}, {%8,%9}, {%0,%1,%2,%3};"
                    : "+f"(c[mt][nt][0]), "+f"(c[mt][nt][1]),
                      "+f"(c[mt][nt][2]), "+f"(c[mt][nt][3])
                    : "r"(af[mt][0]), "r"(af[mt][1]), "r"(af[mt][2]), "r"(af[mt][3]),
                      "r"(bf[nt][0]), "r"(bf[nt][1]));
            }
    };

    // ---- prologue ----
    loadTiles(0, 0);
    asm volatile("cp.async.commit_group;");
    if (NT > 1) {
        loadTiles(1, 1);
        asm volatile("cp.async.commit_group;");
        asm volatile("cp.async.wait_group 1;");
    } else {
        asm volatile("cp.async.wait_group 0;");
    }
    __syncthreads();

    uint32_t afA[4][4], bfA[4][2], afB[4][4], bfB[4][2];
    loadFragA(afA, 0, 0);
    loadFragB(bfA, 0, 0);

    // ---- main loop ----
    for (int it = 0; it < NT; ++it) {
        const int st = it % 3;
        loadFragA(afB, st, 32);                 // second k-step (bytes 32..63)
        loadFragB(bfB, st, 32);
        if (it + 2 < NT) {
            loadTiles((it + 2) % 3, it + 2);
            asm volatile("cp.async.commit_group;");
        }
        mma16(afA, bfA);
        if (it + 1 < NT) {
            if (it + 2 < NT) asm volatile("cp.async.wait_group 1;");
            else             asm volatile("cp.async.wait_group 0;");
            __syncthreads();
            loadFragA(afA, (it + 1) % 3, 0);
            loadFragB(bfA, (it + 1) % 3, 0);
        }
        mma16(afB, bfB);
    }

    // ---- epilogue ----
#pragma unroll
    for (int mt = 0; mt < 4; mt++) {
        const int mrow = m0 + wm * 64 + mt * 16 + g;
#pragma unroll
        for (int nt = 0; nt < 4; nt++) {
            const int ncol = n0 + wn * 32 + nt * 8 + tig * 2;
            storep<EPI>(Cf, Ch, bias, Res, ldc, mrow,     ncol, c[mt][nt][0], c[mt][nt][1]);
            storep<EPI>(Cf, Ch, bias, Res, ldc, mrow + 8, ncol, c[mt][nt][2], c[mt][nt][3]);
        }
    }
}

// ---------------- V transpose: [B*T, H*D] -> [B,H,D,T] ----------------
__global__ void vtrans_kernel(const __half* __restrict__ vs, __half* __restrict__ vd)
{
    __shared__ __half tile[32][33];
    const int z = blockIdx.z, b_ = z >> 3, h_ = z & 7;
    const int t0 = blockIdx.x << 5, d0 = blockIdx.y << 5;
    const int tx = threadIdx.x, ty = threadIdx.y;  // 32 x 8
#pragma unroll
    for (int i = ty; i < 32; i += 8)
        tile[i][tx] = vs[(long long)(b_ * Tt + t0 + i) * 4096 + h_ * 512 + d0 + tx];
    __syncthreads();
#pragma unroll
    for (int i = ty; i < 32; i += 8)
        vd[((long long)z * 512 + d0 + i) * 2048 + t0 + tx] = tile[tx][i];
}

// ---------------- LayerNorm: fp32 copy + fp16 copy ----------------
__global__ void ln_kernel(const float* __restrict__ x, const float* __restrict__ g,
                          const float* __restrict__ b, float* __restrict__ out,
                          __half* __restrict__ outh)
{
    const int row = blockIdx.x;
    const float* xr = x + (long long)row * Ee;
    const int tid = threadIdx.x;  // 256
    float v0 = xr[tid], v1 = xr[tid + 256];
    float s = v0 + v1, sq = v0 * v0 + v1 * v1;
#pragma unroll
    for (int o = 16; o; o >>= 1) {
        s  += __shfl_xor_sync(0xffffffffu, s,  o);
        sq += __shfl_xor_sync(0xffffffffu, sq, o);
    }
    __shared__ float ss[8], sqq[8];
    const int warp = tid >> 5, lane = tid & 31;
    if (lane == 0) { ss[warp] = s; sqq[warp] = sq; }
    __syncthreads();
    if (tid == 0) {
        float a = 0.f, c2 = 0.f;
#pragma unroll
        for (int i = 0; i < 8; i++) { a += ss[i]; c2 += sqq[i]; }
        ss[0] = a; sqq[0] = c2;
    }
    __syncthreads();
    const float mu  = ss[0] * (1.f / 512.f);
    const float var = sqq[0] * (1.f / 512.f) - mu * mu;
    const float r = rsqrtf(var + 1e-5f);
    const float o0 = (v0 - mu) * r * g[tid]       + b[tid];
    const float o1 = (v1 - mu) * r * g[tid + 256] + b[tid + 256];
    out[(long long)row * Ee + tid]        = o0;
    out[(long long)row * Ee + tid + 256]  = o1;
    outh[(long long)row * Ee + tid]       = __float2half_rn(o0);
    outh[(long long)row * Ee + tid + 256] = __float2half_rn(o1);
}

// ---------------- causal softmax: fp32 in, fp16 out ----------------
__global__ void softmax_kernel(const float* __restrict__ S, __half* __restrict__ SH)
{
    const long long r = blockIdx.x;
    const int t = (int)(r & (Tt - 1));
    const float* row = S + (r << 11);
    __half* orow = SH + (r << 11);
    const int len4 = (((t >> 7) + 1) << 7) >> 2;
    const int tid = threadIdx.x;  // 256

    float4 e[2];
    float mx = -1e30f;
#pragma unroll
    for (int c = 0; c < 2; c++) {
        const int i = tid + c * 256;
        if (i < len4) {
            e[c] = *reinterpret_cast<const float4*>(&row[i << 2]);
            mx = fmaxf(fmaxf(fmaxf(e[c].x, e[c].y), fmaxf(e[c].z, e[c].w)), mx);
        }
    }
    __shared__ float redmax[8], redsum[8];
#pragma unroll
    for (int o = 16; o; o >>= 1) mx = fmaxf(mx, __shfl_xor_sync(0xffffffffu, mx, o));
    const int warp = tid >> 5, lane = tid & 31;
    if (lane == 0) redmax[warp] = mx;
    __syncthreads();
    mx = redmax[0];
#pragma unroll
    for (int w = 1; w < 8; w++) mx = fmaxf(mx, redmax[w]);

    float sum = 0.f;
#pragma unroll
    for (int c = 0; c < 2; c++) {
        const int i = tid + c * 256;
        if (i < len4) {
            e[c].x = expf(e[c].x - mx); e[c].y = expf(e[c].y - mx);
            e[c].z = expf(e[c].z - mx); e[c].w = expf(e[c].w - mx);
            sum += (e[c].x + e[c].y) + (e[c].z + e[c].w);
        }
    }
#pragma unroll
    for (int o = 16; o; o >>= 1) sum += __shfl_xor_sync(0xffffffffu, sum, o);
    if (lane == 0) redsum[warp] = sum;
    __syncthreads();
    sum = 0.f;
#pragma unroll
    for (int w = 0; w < 8; w++) sum += redsum[w];
    const float inv = 1.f / sum;
#pragma unroll
    for (int c = 0; c < 2; c++) {
        const int i = tid + c * 256;
        if (i < len4) {
            __half2 h01 = __floats2half2_rn(e[c].x * inv, e[c].y * inv);
            __half2 h23 = __floats2half2_rn(e[c].z * inv, e[c].w * inv);
            uint2 pk;
            pk.x = *reinterpret_cast<uint32_t*>(&h01);
            pk.y = *reinterpret_cast<uint32_t*>(&h23);
            *reinterpret_cast<uint2*>(&orow[i << 2]) = pk;
        }
    }
}

// ---------------- embedding ----------------
__global__ void embed_kernel(const int* __restrict__ tokens, const float* __restrict__ emb,
                             const float* __restrict__ pos, float* __restrict__ y)
{
    const long long idx = (long long)blockIdx.x * 256 + threadIdx.x;
    const int e = (int)(idx & (Ee - 1));
    const long long m = idx >> 9;
    const int t = (int)(m & (Tt - 1));
    const int tok = tokens[m];
    y[idx] = emb[(long long)tok * Ee + e] + pos[(long long)t * Ee + e];
}

// ---------------- head sum + residual ----------------
__global__ void headsum_kernel(const float* __restrict__ ao, float* __restrict__ y)
{
    const long long i4 = (long long)blockIdx.x * 256 + threadIdx.x;
    const long long idx = i4 << 2;
    const int e = (int)(idx & (Ee - 1));
    const long long m = idx >> 9;
    const int b_ = (int)(m >> 11);
    const int t = (int)(m & (Tt - 1));
    float4 s = *reinterpret_cast<const float4*>(&y[idx]);
    const long long base = ((long long)(b_ * Hh) << 20) + ((long long)t << 9) + e;
#pragma unroll
    for (int h = 0; h < Hh; h++) {
        float4 a = *reinterpret_cast<const float4*>(&ao[base + ((long long)h << 20)]);
        s.x += a.x; s.y += a.y; s.z += a.z; s.w += a.w;
    }
    *reinterpret_cast<float4*>(&y[idx]) = s;
}

// ---------------- logits ----------------
__global__ void logits_kernel(const float* __restrict__ y, const float* __restrict__ Wout,
                              const float* __restrict__ bout, float* __restrict__ out)
{
    const int warp = threadIdx.x >> 5, lane = threadIdx.x & 31;
    const int m = blockIdx.x * 8 + warp;
    const float* yr = y + (long long)m * Ee;
    float yreg[16];
#pragma unroll
    for (int i = 0; i < 16; i++) yreg[i] = yr[lane + i * 32];
    for (int n = 0; n < Vv; n++) {
        const float* w = Wout + (long long)n * Ee;
        float s = 0.f;
#pragma unroll
        for (int i = 0; i < 16; i++) s = fmaf(yreg[i], w[lane + i * 32], s);
#pragma unroll
        for (int o = 16; o; o >>= 1) s += __shfl_xor_sync(0xffffffffu, s, o);
        if (lane == 0) out[(long long)m * Vv + n] = s + bout[n];
    }
}

// ---------------- driver ----------------
extern "C" void kernel_launch(void* const* d_in, const int* in_sizes, int n_in,
                              void* d_out, int out_size)
{
    const int*   tokens = (const int*)  d_in[0];
    const float* emb    = (const float*)d_in[1];
    const float* pos    = (const float*)d_in[2];
    const float* ln1_g  = (const float*)d_in[3];
    const float* ln1_b  = (const float*)d_in[4];
    const float* Wq     = (const float*)d_in[5];
    const float* Wk     = (const float*)d_in[6];
    const float* Wv     = (const float*)d_in[7];
    const float* ln2_g  = (const float*)d_in[8];
    const float* ln2_b  = (const float*)d_in[9];
    const float* W1     = (const float*)d_in[10];
    const float* b1     = (const float*)d_in[11];
    const float* W2     = (const float*)d_in[12];
    const float* b2     = (const float*)d_in[13];
    const float* Wout   = (const float*)d_in[14];
    const float* bout   = (const float*)d_in[15];
    float* out = (float*)d_out;

    float *y, *h, *s, *ao;
    __half *hh, *qh, *kh, *vh, *vt, *sh, *uh, *wq, *wk, *wv, *w1, *w2;
    cudaGetSymbolAddress((void**)&y,  g_y);
    cudaGetSymbolAddress((void**)&h,  g_h);
    cudaGetSymbolAddress((void**)&hh, g_hh);
    cudaGetSymbolAddress((void**)&qh, g_qh);
    cudaGetSymbolAddress((void**)&kh, g_kh);
    cudaGetSymbolAddress((void**)&vh, g_vh);
    cudaGetSymbolAddress((void**)&vt, g_vt);
    cudaGetSymbolAddress((void**)&s,  g_s);
    cudaGetSymbolAddress((void**)&sh, g_sh);
    cudaGetSymbolAddress((void**)&ao, g_ao);
    cudaGetSymbolAddress((void**)&uh, g_uh);
    cudaGetSymbolAddress((void**)&wq, g_wq);
    cudaGetSymbolAddress((void**)&wk, g_wk);
    cudaGetSymbolAddress((void**)&wv, g_wv);
    cudaGetSymbolAddress((void**)&w1, g_w1);
    cudaGetSymbolAddress((void**)&w2, g_w2);

    cudaFuncSetAttribute(gemmh<EPI_H,      false, false>, cudaFuncAttributeMaxDynamicSharedMemorySize, GSMEM_B);
    cudaFuncSetAttribute(gemmh<EPI_CAUSAL, false, true >, cudaFuncAttributeMaxDynamicSharedMemorySize, GSMEM_B);
    cudaFuncSetAttribute(gemmh<EPI_F32,    true,  false>, cudaFuncAttributeMaxDynamicSharedMemorySize, GSMEM_B);
    cudaFuncSetAttribute(gemmh<EPI_HRELU,  false, false>, cudaFuncAttributeMaxDynamicSharedMemorySize, GSMEM_B);
    cudaFuncSetAttribute(gemmh<EPI_BIASRES,false, false>, cudaFuncAttributeMaxDynamicSharedMemorySize, GSMEM_B);

    const int MBT = Bb * Tt;  // 8192
    const long long WqkvStride = (long long)Hh * Dd * Ee;
    const int NQKV = Ll * Hh * Dd * Ee;
    const int NMLP = Ll * 4 * Ee * Ee;

    cvtwh_kernel<<<NQKV / 1024, 256>>>(Wq, wq);
    cvtwh_kernel<<<NQKV / 1024, 256>>>(Wk, wk);
    cvtwh_kernel<<<NQKV / 1024, 256>>>(Wv, wv);
    cvtwh_kernel<<<NMLP / 1024, 256>>>(W1, w1);
    cvtwh_kernel<<<NMLP / 1024, 256>>>(W2, w2);

    embed_kernel<<<(MBT * Ee) / 256, 256>>>(tokens, emb, pos, y);

    for (int l = 0; l < Ll; l++) {
        ln_kernel<<<MBT, 256>>>(y, ln1_g + l * Ee, ln1_b + l * Ee, h, hh);

        // QKV projections: [8192,512] x [4096,512]^T -> half plain [8192,4096]
        dim3 gqkv(32, 64);
        gemmh<EPI_H, false, false><<<gqkv, 256, GSMEM_B>>>(
            hh, wq + l * WqkvStride, qh, 512, 512, 4096, 512, 0, 0, 0, nullptr, nullptr);
        gemmh<EPI_H, false, false><<<gqkv, 256, GSMEM_B>>>(
            hh, wk + l * WqkvStride, kh, 512, 512, 4096, 512, 0, 0, 0, nullptr, nullptr);
        gemmh<EPI_H, false, false><<<gqkv, 256, GSMEM_B>>>(
            hh, wv + l * WqkvStride, vh, 512, 512, 4096, 512, 0, 0, 0, nullptr, nullptr);

        vtrans_kernel<<<dim3(Tt / 32, Dd / 32, Bb * Hh), dim3(32, 8)>>>(vh, vt);

        // S = scale * Q K^T (causal), per head via ZQK offsets; fp32 out
        dim3 gqk(16, 16, 32);
        gemmh<EPI_CAUSAL, false, true><<<gqk, 256, GSMEM_B>>>(
            qh, kh, s, 4096, 4096, 2048, 512, 0, 0, (long long)TT, nullptr, nullptr);

        softmax_kernel<<<Bb * Hh * Tt, 256>>>(s, sh);

        // AO = P V (NT with transposed V), causal K-bound; fp32 out
        dim3 gav(4, 16, 32);
        gemmh<EPI_F32, true, false><<<gav, 256, GSMEM_B>>>(
            sh, vt, ao, 2048, 2048, 512, 2048,
            (long long)TT, (long long)(1 << 20), (long long)TD, nullptr, nullptr);

        headsum_kernel<<<(MBT * Ee) / 1024, 256>>>(ao, y);

        ln_kernel<<<MBT, 256>>>(y, ln2_g + l * Ee, ln2_b + l * Ee, h, hh);

        // u = relu(h2 W1^T + b1), half out
        dim3 g1(16, 64);
        gemmh<EPI_HRELU, false, false><<<g1, 256, GSMEM_B>>>(
            hh, w1 + (long long)l * 4 * Ee * Ee, uh, 512, 512, 2048, 512,
            0, 0, 0, b1 + l * 4 * Ee, nullptr);

        // y = u W2^T + b2 + h2, fp32 out
        dim3 g2(4, 64);
        gemmh<EPI_BIASRES, false, false><<<g2, 256, GSMEM_B>>>(
            uh, w2 + (long long)l * Ee * 4 * Ee, y, 2048, 2048, 512, 2048,
            0, 0, 0, b2 + l * Ee, h);
    }

    logits_kernel<<<MBT / 8, 256>>>(y, Wout, bout, out);
}